// round 4
// baseline (speedup 1.0000x reference)
#include <cuda_runtime.h>
#include <cuda_bf16.h>
#include <cstdint>

#define B_  16
#define L_  96
#define D_  512
#define M_  (B_ * L_)
#define ITILE 8
#define NPART (B_ * (L_ / ITILE))

// ---------------- device scratch ------------------------------------------
__device__ float g_AB[M_ * D_];
__device__ float g_C[M_ * D_];
__device__ float g_u[M_];
__device__ float g_v[M_];
__device__ float g_partial[NPART];
__device__ __nv_bfloat16 g_Xh[M_ * D_];
__device__ __nv_bfloat16 g_Xl[M_ * D_];
__device__ __nv_bfloat16 g_Wth[1024 * D_];   // W1 transposed: [n][k]
__device__ __nv_bfloat16 g_Wtl[1024 * D_];

// ---------------- helpers ---------------------------------------------------
__device__ __forceinline__ uint32_t smem_u32(const void* p) {
    uint32_t a;
    asm("{ .reg .u64 t; cvta.to.shared.u64 t, %1; cvt.u32.u64 %0, t; }"
        : "=r"(a) : "l"(p));
    return a;
}
__device__ __forceinline__ void ldsm_x4(uint32_t* r, uint32_t addr) {
    asm volatile("ldmatrix.sync.aligned.m8n8.x4.shared.b16 {%0,%1,%2,%3}, [%4];"
                 : "=r"(r[0]), "=r"(r[1]), "=r"(r[2]), "=r"(r[3]) : "r"(addr));
}
__device__ __forceinline__ void mma_bf16(float* c, const uint32_t* a,
                                         uint32_t b0, uint32_t b1) {
    asm volatile(
        "mma.sync.aligned.m16n8k16.row.col.f32.bf16.bf16.f32 "
        "{%0,%1,%2,%3}, {%4,%5,%6,%7}, {%8,%9}, {%0,%1,%2,%3};"
        : "+f"(c[0]), "+f"(c[1]), "+f"(c[2]), "+f"(c[3])
        : "r"(a[0]), "r"(a[1]), "r"(a[2]), "r"(a[3]), "r"(b0), "r"(b1));
}
__device__ __forceinline__ void cp_async16(uint32_t saddr, const void* gaddr) {
    asm volatile("cp.async.cg.shared.global [%0], [%1], 16;"
                 :: "r"(saddr), "l"(gaddr));
}

// ---------------- kernel A: convert/split X and W1 -------------------------
// blocks [0,768): X split.  blocks [768,1280): W1 transpose+split.
__global__ void convert_kernel(const float* __restrict__ X,
                               const float* __restrict__ W1) {
    const int tid = threadIdx.x;
    if (blockIdx.x < 768) {
        int idx = blockIdx.x * 256 + tid;         // over 196608 float4
        float4 v = ((const float4*)X)[idx];
        __nv_bfloat16 hx = __float2bfloat16(v.x), hy = __float2bfloat16(v.y);
        __nv_bfloat16 hz = __float2bfloat16(v.z), hw = __float2bfloat16(v.w);
        __nv_bfloat16 lx = __float2bfloat16(v.x - __bfloat162float(hx));
        __nv_bfloat16 ly = __float2bfloat16(v.y - __bfloat162float(hy));
        __nv_bfloat16 lz = __float2bfloat16(v.z - __bfloat162float(hz));
        __nv_bfloat16 lw = __float2bfloat16(v.w - __bfloat162float(hw));
        ((__nv_bfloat162*)g_Xh)[idx * 2 + 0] = __nv_bfloat162(hx, hy);
        ((__nv_bfloat162*)g_Xh)[idx * 2 + 1] = __nv_bfloat162(hz, hw);
        ((__nv_bfloat162*)g_Xl)[idx * 2 + 0] = __nv_bfloat162(lx, ly);
        ((__nv_bfloat162*)g_Xl)[idx * 2 + 1] = __nv_bfloat162(lz, lw);
    } else {
        __shared__ float t[32][33];
        const int wb = blockIdx.x - 768;          // 0..511
        const int p  = wb >> 8;                   // 0/1
        const int k0 = ((wb >> 4) & 15) * 32;
        const int n0 = (wb & 15) * 32;
        const int tx = tid & 31, ty = tid >> 5;   // (32, 8)
#pragma unroll
        for (int r = 0; r < 32; r += 8)
            t[ty + r][tx] = W1[(size_t)(p * 512 + k0 + ty + r) * 512 + n0 + tx];
        __syncthreads();
#pragma unroll
        for (int r = 0; r < 32; r += 8) {
            float v = t[tx][ty + r];
            __nv_bfloat16 h = __float2bfloat16(v);
            __nv_bfloat16 l = __float2bfloat16(v - __bfloat162float(h));
            size_t o = (size_t)(p * 512 + n0 + ty + r) * 512 + k0 + tx;
            g_Wth[o] = h;
            g_Wtl[o] = l;
        }
    }
}

// ---------------- kernel B: bf16-split GEMM via mma.sync --------------------
// out[m,n], m<1536, n<1024: n<512 -> g_AB (+b1), n>=512 -> g_C
#define BK 32
#define ASTRIDE 80                 // bytes per smem row (40 bf16)
#define TILE_B (128 * ASTRIDE)     // 10240
#define BUFB   (4 * TILE_B)        // Ah, Al, Bh, Bl
#define GEMM_SMEM (2 * BUFB)       // 81920

__global__ void __launch_bounds__(256, 1)
gemm_mma_kernel(const float* __restrict__ b1) {
    extern __shared__ char smem[];
    const uint32_t smem_base = smem_u32(smem);
    const int tid = threadIdx.x, wid = tid >> 5, lane = tid & 31;
    const int n0 = blockIdx.x * 128;
    const int m0 = blockIdx.y * 128;
    const int m_off = (wid & 3) * 32;     // 4 M-warps
    const int n_off = (wid >> 2) * 64;    // 2 N-warps

    const __nv_bfloat16* srcs[4] = {
        g_Xh  + (size_t)m0 * 512, g_Xl  + (size_t)m0 * 512,
        g_Wth + (size_t)n0 * 512, g_Wtl + (size_t)n0 * 512};

    auto prefetch = [&](int c, int buf) {
        const uint32_t sm0 = smem_base + buf * BUFB;
#pragma unroll
        for (int it = 0; it < 8; it++) {
            int t = it * 256 + tid;
            int s = t >> 9, r = (t >> 2) & 127, q = t & 3;
            cp_async16(sm0 + s * TILE_B + r * ASTRIDE + q * 16,
                       srcs[s] + (size_t)r * 512 + c * BK + q * 8);
        }
    };

    float acc[2][8][4];
#pragma unroll
    for (int i = 0; i < 2; i++)
#pragma unroll
        for (int j = 0; j < 8; j++)
#pragma unroll
            for (int k = 0; k < 4; k++) acc[i][j][k] = 0.f;

    // per-lane ldmatrix address components
    const int grp = lane >> 3, ln8 = lane & 7;
    const int a_row = (grp & 1) * 8 + ln8;     // + m base
    const int a_kB  = (grp >> 1) * 16;         // k byte offset within step
    const int b_row = ((grp >> 1) & 1) * 8 + ln8;
    const int b_kB  = (grp & 1) * 16;

    prefetch(0, 0);
    asm volatile("cp.async.commit_group;" ::: "memory");

    for (int c = 0; c < 16; c++) {
        const int buf = c & 1;
        if (c + 1 < 16) {
            prefetch(c + 1, buf ^ 1);
            asm volatile("cp.async.commit_group;" ::: "memory");
            asm volatile("cp.async.wait_group 1;" ::: "memory");
        } else {
            asm volatile("cp.async.wait_group 0;" ::: "memory");
        }
        __syncthreads();

        const uint32_t base = smem_base + buf * BUFB;
#pragma unroll
        for (int p = 0; p < 3; p++) {                 // hh, hl, lh
            const uint32_t Ab = base + ((p == 2) ? TILE_B : 0);
            const uint32_t Bb = base + ((p == 1) ? 3 : 2) * TILE_B;
#pragma unroll
            for (int ks = 0; ks < 2; ks++) {
                const int kB = ks * 32;               // 16 bf16 = 32B
                uint32_t a[2][4];
#pragma unroll
                for (int fm = 0; fm < 2; fm++)
                    ldsm_x4(a[fm], Ab + (m_off + fm * 16 + a_row) * ASTRIDE
                                      + kB + a_kB);
                uint32_t b[4][4];
#pragma unroll
                for (int fp = 0; fp < 4; fp++)
                    ldsm_x4(b[fp], Bb + (n_off + fp * 16 + b_row) * ASTRIDE
                                      + kB + b_kB);
#pragma unroll
                for (int fm = 0; fm < 2; fm++)
#pragma unroll
                    for (int fp = 0; fp < 4; fp++) {
                        mma_bf16(acc[fm][2 * fp + 0], a[fm], b[fp][0], b[fp][1]);
                        mma_bf16(acc[fm][2 * fp + 1], a[fm], b[fp][2], b[fp][3]);
                    }
            }
        }
        __syncthreads();
    }

    // epilogue
    const int r0 = lane >> 2, cc = (lane & 3) * 2;
#pragma unroll
    for (int fm = 0; fm < 2; fm++) {
        const int mrow = m0 + m_off + fm * 16 + r0;
#pragma unroll
        for (int fn = 0; fn < 8; fn++) {
            const int gcol = n0 + n_off + fn * 8 + cc;
            const float* a4 = acc[fm][fn];
            if (n0 < 512) {
                float2 bb = *(const float2*)&b1[gcol];
                *(float2*)&g_AB[(size_t)mrow * 512 + gcol] =
                    make_float2(a4[0] + bb.x, a4[1] + bb.y);
                *(float2*)&g_AB[(size_t)(mrow + 8) * 512 + gcol] =
                    make_float2(a4[2] + bb.x, a4[3] + bb.y);
            } else {
                *(float2*)&g_C[(size_t)mrow * 512 + gcol - 512] =
                    make_float2(a4[0], a4[1]);
                *(float2*)&g_C[(size_t)(mrow + 8) * 512 + gcol - 512] =
                    make_float2(a4[2], a4[3]);
            }
        }
    }
}

// ---------------- kernel 2: per-row dot products u, v ----------------------
__global__ void rowdot_kernel(const float* __restrict__ W2) {
    const int gw = (blockIdx.x * blockDim.x + threadIdx.x) >> 5;
    const int lane = threadIdx.x & 31;
    if (gw >= M_) return;
    const float* ab = &g_AB[(size_t)gw * D_];
    const float* cc = &g_C[(size_t)gw * D_];
    float su = 0.f, sv = 0.f;
#pragma unroll 4
    for (int h = lane; h < D_; h += 32) {
        float w = W2[h];
        su = fmaf(ab[h], w, su);
        sv = fmaf(cc[h], w, sv);
    }
#pragma unroll
    for (int o = 16; o > 0; o >>= 1) {
        su += __shfl_xor_sync(0xffffffffu, su, o);
        sv += __shfl_xor_sync(0xffffffffu, sv, o);
    }
    if (lane == 0) { g_u[gw] = su; g_v[gw] = sv; }
}

// ---------------- kernel 3: pairwise |.| reduction + fused softmax-CE ------
__global__ void pairwise_kernel(const float* __restrict__ W2,
                                const float* __restrict__ b2,
                                const int* __restrict__ order) {
    __shared__ float Cs[16][D_];
    __shared__ float rowbuf[ITILE][L_];
    __shared__ int   ord[L_];
    __shared__ float vsh[L_];
    __shared__ float wpart[ITILE];

    const int b  = blockIdx.y;
    const int i0 = blockIdx.x * ITILE;
    const int tid = threadIdx.x;
    const int warp = tid >> 5;
    const int lane = tid & 31;
    const int i = i0 + warp;

    if (tid < L_) {
        ord[tid] = order[b * L_ + tid];
        vsh[tid] = g_v[b * L_ + tid];
    }

    const float* abrow = &g_AB[(size_t)(b * L_ + i) * D_];
    float4 ab4[4], w24[4];
#pragma unroll
    for (int t = 0; t < 4; t++) {
        ab4[t] = *(const float4*)&abrow[t * 128 + lane * 4];
        w24[t] = *(const float4*)&W2[t * 128 + lane * 4];
    }
    const float u   = g_u[b * L_ + i];
    const float b2v = b2[0];

    for (int jc = 0; jc < L_; jc += 16) {
        __syncthreads();
        for (int t = tid; t < 16 * 128; t += 256) {
            int r = t >> 7, c4 = t & 127;
            ((float4*)&Cs[r][0])[c4] =
                ((const float4*)&g_C[(size_t)(b * L_ + jc + r) * D_])[c4];
        }
        __syncthreads();

        for (int jj = 0; jj < 16; jj++) {
            float acc0 = 0.f, acc1 = 0.f;
#pragma unroll
            for (int t = 0; t < 4; t++) {
                float4 cv = *(const float4*)&Cs[jj][t * 128 + lane * 4];
                float s;
                s = ab4[t].x + cv.x; acc0 = fmaf(fabsf(s), w24[t].x, acc0);
                s = ab4[t].y + cv.y; acc1 = fmaf(fabsf(s), w24[t].y, acc1);
                s = ab4[t].z + cv.z; acc0 = fmaf(fabsf(s), w24[t].z, acc0);
                s = ab4[t].w + cv.w; acc1 = fmaf(fabsf(s), w24[t].w, acc1);
            }
            float acc = acc0 + acc1;
#pragma unroll
            for (int o = 16; o > 0; o >>= 1)
                acc += __shfl_xor_sync(0xffffffffu, acc, o);
            if (lane == 0) {
                int j = jc + jj;
                rowbuf[warp][j] = 0.55f * (u + vsh[j]) + 0.45f * acc + b2v;
            }
        }
    }
    __syncthreads();

    float l0 = rowbuf[warp][lane];
    float l1 = rowbuf[warp][lane + 32];
    float l2 = rowbuf[warp][lane + 64];
    float m = fmaxf(l0, fmaxf(l1, l2));
#pragma unroll
    for (int o = 16; o > 0; o >>= 1)
        m = fmaxf(m, __shfl_xor_sync(0xffffffffu, m, o));
    float s = expf(l0 - m) + expf(l1 - m) + expf(l2 - m);
#pragma unroll
    for (int o = 16; o > 0; o >>= 1)
        s += __shfl_xor_sync(0xffffffffu, s, o);
    float lse = m + logf(s);

    int oi = ord[i];
    int o0 = ord[lane], o1 = ord[lane + 32], o2 = ord[lane + 64];
    unsigned t0 = __ballot_sync(0xffffffffu, o0 == oi + 1);
    unsigned t1 = __ballot_sync(0xffffffffu, o1 == oi + 1);
    unsigned t2 = __ballot_sync(0xffffffffu, o2 == oi + 1);
    int tgt = t0 ? (__ffs(t0) - 1)
                 : (t1 ? (31 + __ffs(t1)) : (t2 ? (63 + __ffs(t2)) : 0));

    int mx = max(o0, max(o1, o2));
#pragma unroll
    for (int o = 16; o > 0; o >>= 1)
        mx = max(mx, __shfl_xor_sync(0xffffffffu, mx, o));
    unsigned M0 = __ballot_sync(0xffffffffu, o0 == mx);
    unsigned M1 = __ballot_sync(0xffffffffu, o1 == mx);
    unsigned M2 = __ballot_sync(0xffffffffu, o2 == mx);
    int last = M0 ? (__ffs(M0) - 1) : (M1 ? (31 + __ffs(M1)) : (63 + __ffs(M2)));

    float contrib = (i == last) ? 0.f : (lse - rowbuf[warp][tgt]);
    if (lane == 0) wpart[warp] = contrib;
    __syncthreads();
    if (tid == 0) {
        float ssum = 0.f;
#pragma unroll
        for (int w = 0; w < ITILE; w++) ssum += wpart[w];
        g_partial[b * (L_ / ITILE) + blockIdx.x] = ssum;
    }
}

// ---------------- kernel 4: deterministic final reduction ------------------
__global__ void finalize_kernel(float* __restrict__ out) {
    __shared__ float sh[NPART];
    int t = threadIdx.x;
    if (t < NPART) sh[t] = g_partial[t];
    __syncthreads();
    if (t == 0) {
        float s = 0.f;
        for (int k = 0; k < NPART; k++) s += sh[k];
        out[0] = s * (1.0f / (16.0f * 95.0f));
    }
}

// ---------------- launcher --------------------------------------------------
extern "C" void kernel_launch(void* const* d_in, const int* in_sizes, int n_in,
                              void* d_out, int out_size) {
    const float* X    = (const float*)d_in[0];
    const float* W1   = (const float*)d_in[1];
    const float* b1   = (const float*)d_in[2];
    const float* W2   = (const float*)d_in[3];
    const float* b2   = (const float*)d_in[4];
    const int*   order = (const int*)d_in[6];

    static bool attr_set = false;
    if (!attr_set) {
        cudaFuncSetAttribute(gemm_mma_kernel,
                             cudaFuncAttributeMaxDynamicSharedMemorySize, GEMM_SMEM);
        attr_set = true;
    }

    convert_kernel<<<1280, 256>>>(X, W1);
    gemm_mma_kernel<<<dim3(8, 12), 256, GEMM_SMEM>>>(b1);
    rowdot_kernel<<<192, 256>>>(W2);
    pairwise_kernel<<<dim3(L_ / ITILE, B_), 256>>>(W2, b2, order);
    finalize_kernel<<<1, 256>>>((float*)d_out);
}

// round 5
// speedup vs baseline: 1.5124x; 1.5124x over previous
#include <cuda_runtime.h>
#include <cuda_bf16.h>
#include <cstdint>

#define B_  16
#define L_  96
#define D_  512
#define M_  (B_ * L_)
#define ITILE 8
#define NPART (B_ * (L_ / ITILE))

// ---------------- device scratch ------------------------------------------
__device__ float g_AB[M_ * D_];
__device__ float g_C[M_ * D_];
__device__ float g_u[M_];
__device__ float g_v[M_];
__device__ float g_partial[NPART];
__device__ __nv_bfloat16 g_Xh[M_ * D_];
__device__ __nv_bfloat16 g_Xl[M_ * D_];
__device__ __nv_bfloat16 g_Wth[1024 * D_];   // W1 transposed: [n][k]
__device__ __nv_bfloat16 g_Wtl[1024 * D_];

// ---------------- helpers ---------------------------------------------------
__device__ __forceinline__ uint32_t smem_u32(const void* p) {
    uint32_t a;
    asm("{ .reg .u64 t; cvta.to.shared.u64 t, %1; cvt.u32.u64 %0, t; }"
        : "=r"(a) : "l"(p));
    return a;
}
__device__ __forceinline__ void ldsm_x4(uint32_t* r, uint32_t addr) {
    asm volatile("ldmatrix.sync.aligned.m8n8.x4.shared.b16 {%0,%1,%2,%3}, [%4];"
                 : "=r"(r[0]), "=r"(r[1]), "=r"(r[2]), "=r"(r[3]) : "r"(addr));
}
__device__ __forceinline__ void mma_bf16(float* c, const uint32_t* a,
                                         uint32_t b0, uint32_t b1) {
    asm volatile(
        "mma.sync.aligned.m16n8k16.row.col.f32.bf16.bf16.f32 "
        "{%0,%1,%2,%3}, {%4,%5,%6,%7}, {%8,%9}, {%0,%1,%2,%3};"
        : "+f"(c[0]), "+f"(c[1]), "+f"(c[2]), "+f"(c[3])
        : "r"(a[0]), "r"(a[1]), "r"(a[2]), "r"(a[3]), "r"(b0), "r"(b1));
}
__device__ __forceinline__ void cp_async16(uint32_t saddr, const void* gaddr) {
    asm volatile("cp.async.cg.shared.global [%0], [%1], 16;"
                 :: "r"(saddr), "l"(gaddr));
}

// ---------------- kernel A: convert/split X and W1 -------------------------
// blocks [0,768): X split.  blocks [768,1280): W1 transpose+split.
__global__ void convert_kernel(const float* __restrict__ X,
                               const float* __restrict__ W1) {
    const int tid = threadIdx.x;
    if (blockIdx.x < 768) {
        int idx = blockIdx.x * 256 + tid;         // over 196608 float4
        float4 v = ((const float4*)X)[idx];
        __nv_bfloat16 hx = __float2bfloat16(v.x), hy = __float2bfloat16(v.y);
        __nv_bfloat16 hz = __float2bfloat16(v.z), hw = __float2bfloat16(v.w);
        __nv_bfloat16 lx = __float2bfloat16(v.x - __bfloat162float(hx));
        __nv_bfloat16 ly = __float2bfloat16(v.y - __bfloat162float(hy));
        __nv_bfloat16 lz = __float2bfloat16(v.z - __bfloat162float(hz));
        __nv_bfloat16 lw = __float2bfloat16(v.w - __bfloat162float(hw));
        ((__nv_bfloat162*)g_Xh)[idx * 2 + 0] = __nv_bfloat162(hx, hy);
        ((__nv_bfloat162*)g_Xh)[idx * 2 + 1] = __nv_bfloat162(hz, hw);
        ((__nv_bfloat162*)g_Xl)[idx * 2 + 0] = __nv_bfloat162(lx, ly);
        ((__nv_bfloat162*)g_Xl)[idx * 2 + 1] = __nv_bfloat162(lz, lw);
    } else {
        __shared__ float t[32][33];
        const int wb = blockIdx.x - 768;          // 0..511
        const int p  = wb >> 8;                   // 0/1
        const int k0 = ((wb >> 4) & 15) * 32;
        const int n0 = (wb & 15) * 32;
        const int tx = tid & 31, ty = tid >> 5;   // (32, 8)
#pragma unroll
        for (int r = 0; r < 32; r += 8)
            t[ty + r][tx] = W1[(size_t)(p * 512 + k0 + ty + r) * 512 + n0 + tx];
        __syncthreads();
#pragma unroll
        for (int r = 0; r < 32; r += 8) {
            float v = t[tx][ty + r];
            __nv_bfloat16 h = __float2bfloat16(v);
            __nv_bfloat16 l = __float2bfloat16(v - __bfloat162float(h));
            size_t o = (size_t)(p * 512 + n0 + ty + r) * 512 + k0 + tx;
            g_Wth[o] = h;
            g_Wtl[o] = l;
        }
    }
}

// ---------------- kernel B: bf16-split GEMM via mma.sync --------------------
// out[m,n], m<1536, n<1024: n<512 -> g_AB (+b1), n>=512 -> g_C
#define BK 32
#define ASTRIDE 80                 // bytes per smem row (40 bf16)
#define TILE_B (128 * ASTRIDE)     // 10240
#define BUFB   (4 * TILE_B)        // Ah, Al, Bh, Bl
#define GEMM_SMEM (2 * BUFB)       // 81920

__global__ void __launch_bounds__(256, 1)
gemm_mma_kernel(const float* __restrict__ b1) {
    extern __shared__ char smem[];
    const uint32_t smem_base = smem_u32(smem);
    const int tid = threadIdx.x, wid = tid >> 5, lane = tid & 31;
    const int n0 = blockIdx.x * 128;
    const int m0 = blockIdx.y * 128;
    const int m_off = (wid & 3) * 32;     // 4 M-warps
    const int n_off = (wid >> 2) * 64;    // 2 N-warps

    const __nv_bfloat16* srcs[4] = {
        g_Xh  + (size_t)m0 * 512, g_Xl  + (size_t)m0 * 512,
        g_Wth + (size_t)n0 * 512, g_Wtl + (size_t)n0 * 512};

    auto prefetch = [&](int c, int buf) {
        const uint32_t sm0 = smem_base + buf * BUFB;
#pragma unroll
        for (int it = 0; it < 8; it++) {
            int t = it * 256 + tid;
            int s = t >> 9, r = (t >> 2) & 127, q = t & 3;
            cp_async16(sm0 + s * TILE_B + r * ASTRIDE + q * 16,
                       srcs[s] + (size_t)r * 512 + c * BK + q * 8);
        }
    };

    float acc[2][8][4];
#pragma unroll
    for (int i = 0; i < 2; i++)
#pragma unroll
        for (int j = 0; j < 8; j++)
#pragma unroll
            for (int k = 0; k < 4; k++) acc[i][j][k] = 0.f;

    // per-lane ldmatrix address components
    const int grp = lane >> 3, ln8 = lane & 7;
    const int a_row = (grp & 1) * 8 + ln8;     // + m base
    const int a_kB  = (grp >> 1) * 16;         // k byte offset within step
    const int b_row = ((grp >> 1) & 1) * 8 + ln8;
    const int b_kB  = (grp & 1) * 16;

    prefetch(0, 0);
    asm volatile("cp.async.commit_group;" ::: "memory");

    for (int c = 0; c < 16; c++) {
        const int buf = c & 1;
        if (c + 1 < 16) {
            prefetch(c + 1, buf ^ 1);
            asm volatile("cp.async.commit_group;" ::: "memory");
            asm volatile("cp.async.wait_group 1;" ::: "memory");
        } else {
            asm volatile("cp.async.wait_group 0;" ::: "memory");
        }
        __syncthreads();

        const uint32_t base = smem_base + buf * BUFB;
#pragma unroll
        for (int p = 0; p < 3; p++) {                 // hh, hl, lh
            const uint32_t Ab = base + ((p == 2) ? TILE_B : 0);
            const uint32_t Bb = base + ((p == 1) ? 3 : 2) * TILE_B;
#pragma unroll
            for (int ks = 0; ks < 2; ks++) {
                const int kB = ks * 32;               // 16 bf16 = 32B
                uint32_t a[2][4];
#pragma unroll
                for (int fm = 0; fm < 2; fm++)
                    ldsm_x4(a[fm], Ab + (m_off + fm * 16 + a_row) * ASTRIDE
                                      + kB + a_kB);
                uint32_t b[4][4];
#pragma unroll
                for (int fp = 0; fp < 4; fp++)
                    ldsm_x4(b[fp], Bb + (n_off + fp * 16 + b_row) * ASTRIDE
                                      + kB + b_kB);
#pragma unroll
                for (int fm = 0; fm < 2; fm++)
#pragma unroll
                    for (int fp = 0; fp < 4; fp++) {
                        mma_bf16(acc[fm][2 * fp + 0], a[fm], b[fp][0], b[fp][1]);
                        mma_bf16(acc[fm][2 * fp + 1], a[fm], b[fp][2], b[fp][3]);
                    }
            }
        }
        __syncthreads();
    }

    // epilogue
    const int r0 = lane >> 2, cc = (lane & 3) * 2;
#pragma unroll
    for (int fm = 0; fm < 2; fm++) {
        const int mrow = m0 + m_off + fm * 16 + r0;
#pragma unroll
        for (int fn = 0; fn < 8; fn++) {
            const int gcol = n0 + n_off + fn * 8 + cc;
            const float* a4 = acc[fm][fn];
            if (n0 < 512) {
                float2 bb = *(const float2*)&b1[gcol];
                *(float2*)&g_AB[(size_t)mrow * 512 + gcol] =
                    make_float2(a4[0] + bb.x, a4[1] + bb.y);
                *(float2*)&g_AB[(size_t)(mrow + 8) * 512 + gcol] =
                    make_float2(a4[2] + bb.x, a4[3] + bb.y);
            } else {
                *(float2*)&g_C[(size_t)mrow * 512 + gcol - 512] =
                    make_float2(a4[0], a4[1]);
                *(float2*)&g_C[(size_t)(mrow + 8) * 512 + gcol - 512] =
                    make_float2(a4[2], a4[3]);
            }
        }
    }
}

// ---------------- kernel 2: per-row dot products u, v ----------------------
__global__ void rowdot_kernel(const float* __restrict__ W2) {
    const int gw = (blockIdx.x * blockDim.x + threadIdx.x) >> 5;
    const int lane = threadIdx.x & 31;
    if (gw >= M_) return;
    const float* ab = &g_AB[(size_t)gw * D_];
    const float* cc = &g_C[(size_t)gw * D_];
    float su = 0.f, sv = 0.f;
#pragma unroll 4
    for (int h = lane; h < D_; h += 32) {
        float w = W2[h];
        su = fmaf(ab[h], w, su);
        sv = fmaf(cc[h], w, sv);
    }
#pragma unroll
    for (int o = 16; o > 0; o >>= 1) {
        su += __shfl_xor_sync(0xffffffffu, su, o);
        sv += __shfl_xor_sync(0xffffffffu, sv, o);
    }
    if (lane == 0) { g_u[gw] = su; g_v[gw] = sv; }
}

// ---------------- kernel 3: pairwise |.| reduction + fused softmax-CE ------
__global__ void pairwise_kernel(const float* __restrict__ W2,
                                const float* __restrict__ b2,
                                const int* __restrict__ order) {
    __shared__ float Cs[16][D_];
    __shared__ float rowbuf[ITILE][L_];
    __shared__ int   ord[L_];
    __shared__ float vsh[L_];
    __shared__ float wpart[ITILE];

    const int b  = blockIdx.y;
    const int i0 = blockIdx.x * ITILE;
    const int tid = threadIdx.x;
    const int warp = tid >> 5;
    const int lane = tid & 31;
    const int i = i0 + warp;

    if (tid < L_) {
        ord[tid] = order[b * L_ + tid];
        vsh[tid] = g_v[b * L_ + tid];
    }

    const float* abrow = &g_AB[(size_t)(b * L_ + i) * D_];
    float4 ab4[4], w24[4];
#pragma unroll
    for (int t = 0; t < 4; t++) {
        ab4[t] = *(const float4*)&abrow[t * 128 + lane * 4];
        w24[t] = *(const float4*)&W2[t * 128 + lane * 4];
    }
    const float u   = g_u[b * L_ + i];
    const float b2v = b2[0];

    for (int jc = 0; jc < L_; jc += 16) {
        __syncthreads();
        for (int t = tid; t < 16 * 128; t += 256) {
            int r = t >> 7, c4 = t & 127;
            ((float4*)&Cs[r][0])[c4] =
                ((const float4*)&g_C[(size_t)(b * L_ + jc + r) * D_])[c4];
        }
        __syncthreads();

        for (int jj = 0; jj < 16; jj++) {
            float acc0 = 0.f, acc1 = 0.f;
#pragma unroll
            for (int t = 0; t < 4; t++) {
                float4 cv = *(const float4*)&Cs[jj][t * 128 + lane * 4];
                float s;
                s = ab4[t].x + cv.x; acc0 = fmaf(fabsf(s), w24[t].x, acc0);
                s = ab4[t].y + cv.y; acc1 = fmaf(fabsf(s), w24[t].y, acc1);
                s = ab4[t].z + cv.z; acc0 = fmaf(fabsf(s), w24[t].z, acc0);
                s = ab4[t].w + cv.w; acc1 = fmaf(fabsf(s), w24[t].w, acc1);
            }
            float acc = acc0 + acc1;
#pragma unroll
            for (int o = 16; o > 0; o >>= 1)
                acc += __shfl_xor_sync(0xffffffffu, acc, o);
            if (lane == 0) {
                int j = jc + jj;
                rowbuf[warp][j] = 0.55f * (u + vsh[j]) + 0.45f * acc + b2v;
            }
        }
    }
    __syncthreads();

    float l0 = rowbuf[warp][lane];
    float l1 = rowbuf[warp][lane + 32];
    float l2 = rowbuf[warp][lane + 64];
    float m = fmaxf(l0, fmaxf(l1, l2));
#pragma unroll
    for (int o = 16; o > 0; o >>= 1)
        m = fmaxf(m, __shfl_xor_sync(0xffffffffu, m, o));
    float s = expf(l0 - m) + expf(l1 - m) + expf(l2 - m);
#pragma unroll
    for (int o = 16; o > 0; o >>= 1)
        s += __shfl_xor_sync(0xffffffffu, s, o);
    float lse = m + logf(s);

    int oi = ord[i];
    int o0 = ord[lane], o1 = ord[lane + 32], o2 = ord[lane + 64];
    unsigned t0 = __ballot_sync(0xffffffffu, o0 == oi + 1);
    unsigned t1 = __ballot_sync(0xffffffffu, o1 == oi + 1);
    unsigned t2 = __ballot_sync(0xffffffffu, o2 == oi + 1);
    int tgt = t0 ? (__ffs(t0) - 1)
                 : (t1 ? (31 + __ffs(t1)) : (t2 ? (63 + __ffs(t2)) : 0));

    int mx = max(o0, max(o1, o2));
#pragma unroll
    for (int o = 16; o > 0; o >>= 1)
        mx = max(mx, __shfl_xor_sync(0xffffffffu, mx, o));
    unsigned M0 = __ballot_sync(0xffffffffu, o0 == mx);
    unsigned M1 = __ballot_sync(0xffffffffu, o1 == mx);
    unsigned M2 = __ballot_sync(0xffffffffu, o2 == mx);
    int last = M0 ? (__ffs(M0) - 1) : (M1 ? (31 + __ffs(M1)) : (63 + __ffs(M2)));

    float contrib = (i == last) ? 0.f : (lse - rowbuf[warp][tgt]);
    if (lane == 0) wpart[warp] = contrib;
    __syncthreads();
    if (tid == 0) {
        float ssum = 0.f;
#pragma unroll
        for (int w = 0; w < ITILE; w++) ssum += wpart[w];
        g_partial[b * (L_ / ITILE) + blockIdx.x] = ssum;
    }
}

// ---------------- kernel 4: deterministic final reduction ------------------
__global__ void finalize_kernel(float* __restrict__ out) {
    __shared__ float sh[NPART];
    int t = threadIdx.x;
    if (t < NPART) sh[t] = g_partial[t];
    __syncthreads();
    if (t == 0) {
        float s = 0.f;
        for (int k = 0; k < NPART; k++) s += sh[k];
        out[0] = s * (1.0f / (16.0f * 95.0f));
    }
}

// ---------------- launcher --------------------------------------------------
extern "C" void kernel_launch(void* const* d_in, const int* in_sizes, int n_in,
                              void* d_out, int out_size) {
    const float* X    = (const float*)d_in[0];
    const float* W1   = (const float*)d_in[1];
    const float* b1   = (const float*)d_in[2];
    const float* W2   = (const float*)d_in[3];
    const float* b2   = (const float*)d_in[4];
    const int*   order = (const int*)d_in[6];

    static bool attr_set = false;
    if (!attr_set) {
        cudaFuncSetAttribute(gemm_mma_kernel,
                             cudaFuncAttributeMaxDynamicSharedMemorySize, GEMM_SMEM);
        attr_set = true;
    }

    convert_kernel<<<1280, 256>>>(X, W1);
    gemm_mma_kernel<<<dim3(8, 12), 256, GEMM_SMEM>>>(b1);
    rowdot_kernel<<<192, 256>>>(W2);
    pairwise_kernel<<<dim3(L_ / ITILE, B_), 256>>>(W2, b2, order);
    finalize_kernel<<<1, 256>>>((float*)d_out);
}

// round 6
// speedup vs baseline: 1.5331x; 1.0137x over previous
#include <cuda_runtime.h>
#include <cuda_bf16.h>
#include <cstdint>

#define B_  16
#define L_  96
#define D_  512
#define M_  (B_ * L_)
#define ITILE 8
#define NPART (B_ * (L_ / ITILE))

// ---------------- device scratch ------------------------------------------
__device__ float g_AB[M_ * D_];
__device__ float g_C[M_ * D_];
__device__ float g_u[M_];
__device__ float g_v[M_];
__device__ float g_partial[NPART];
__device__ __nv_bfloat16 g_Xh[M_ * D_];
__device__ __nv_bfloat16 g_Xl[M_ * D_];
__device__ __nv_bfloat16 g_Wth[1024 * D_];   // W1 transposed: [n][k]
__device__ __nv_bfloat16 g_Wtl[1024 * D_];

// ---------------- helpers ---------------------------------------------------
__device__ __forceinline__ uint32_t smem_u32(const void* p) {
    uint32_t a;
    asm("{ .reg .u64 t; cvta.to.shared.u64 t, %1; cvt.u32.u64 %0, t; }"
        : "=r"(a) : "l"(p));
    return a;
}
__device__ __forceinline__ void ldsm_x4(uint32_t* r, uint32_t addr) {
    asm volatile("ldmatrix.sync.aligned.m8n8.x4.shared.b16 {%0,%1,%2,%3}, [%4];"
                 : "=r"(r[0]), "=r"(r[1]), "=r"(r[2]), "=r"(r[3]) : "r"(addr));
}
__device__ __forceinline__ void mma_bf16(float* c, const uint32_t* a,
                                         uint32_t b0, uint32_t b1) {
    asm volatile(
        "mma.sync.aligned.m16n8k16.row.col.f32.bf16.bf16.f32 "
        "{%0,%1,%2,%3}, {%4,%5,%6,%7}, {%8,%9}, {%0,%1,%2,%3};"
        : "+f"(c[0]), "+f"(c[1]), "+f"(c[2]), "+f"(c[3])
        : "r"(a[0]), "r"(a[1]), "r"(a[2]), "r"(a[3]), "r"(b0), "r"(b1));
}
__device__ __forceinline__ void cp_async16(uint32_t saddr, const void* gaddr) {
    asm volatile("cp.async.cg.shared.global [%0], [%1], 16;"
                 :: "r"(saddr), "l"(gaddr));
}

// ---------------- kernel A: convert/split X and W1 -------------------------
// blocks [0,768): X split.  blocks [768,1280): W1 transpose+split.
__global__ void convert_kernel(const float* __restrict__ X,
                               const float* __restrict__ W1) {
    const int tid = threadIdx.x;
    if (blockIdx.x < 768) {
        int idx = blockIdx.x * 256 + tid;         // over 196608 float4
        float4 v = ((const float4*)X)[idx];
        __nv_bfloat16 hx = __float2bfloat16(v.x), hy = __float2bfloat16(v.y);
        __nv_bfloat16 hz = __float2bfloat16(v.z), hw = __float2bfloat16(v.w);
        __nv_bfloat16 lx = __float2bfloat16(v.x - __bfloat162float(hx));
        __nv_bfloat16 ly = __float2bfloat16(v.y - __bfloat162float(hy));
        __nv_bfloat16 lz = __float2bfloat16(v.z - __bfloat162float(hz));
        __nv_bfloat16 lw = __float2bfloat16(v.w - __bfloat162float(hw));
        ((__nv_bfloat162*)g_Xh)[idx * 2 + 0] = __nv_bfloat162(hx, hy);
        ((__nv_bfloat162*)g_Xh)[idx * 2 + 1] = __nv_bfloat162(hz, hw);
        ((__nv_bfloat162*)g_Xl)[idx * 2 + 0] = __nv_bfloat162(lx, ly);
        ((__nv_bfloat162*)g_Xl)[idx * 2 + 1] = __nv_bfloat162(lz, lw);
    } else {
        __shared__ float t[32][33];
        const int wb = blockIdx.x - 768;          // 0..511
        const int p  = wb >> 8;                   // 0/1
        const int k0 = ((wb >> 4) & 15) * 32;
        const int n0 = (wb & 15) * 32;
        const int tx = tid & 31, ty = tid >> 5;   // (32, 8)
#pragma unroll
        for (int r = 0; r < 32; r += 8)
            t[ty + r][tx] = W1[(size_t)(p * 512 + k0 + ty + r) * 512 + n0 + tx];
        __syncthreads();
#pragma unroll
        for (int r = 0; r < 32; r += 8) {
            float v = t[tx][ty + r];
            __nv_bfloat16 h = __float2bfloat16(v);
            __nv_bfloat16 l = __float2bfloat16(v - __bfloat162float(h));
            size_t o = (size_t)(p * 512 + n0 + ty + r) * 512 + k0 + tx;
            g_Wth[o] = h;
            g_Wtl[o] = l;
        }
    }
}

// ---------------- kernel B: bf16-split GEMM via mma.sync --------------------
// out[m,n], m<1536, n<1024: n<512 -> g_AB (+b1), n>=512 -> g_C
#define BK 32
#define ASTRIDE 80                 // bytes per smem row (40 bf16)
#define TILE_B (128 * ASTRIDE)     // 10240
#define BUFB   (4 * TILE_B)        // Ah, Al, Bh, Bl
#define GEMM_SMEM (2 * BUFB)       // 81920

__global__ void __launch_bounds__(256, 1)
gemm_mma_kernel(const float* __restrict__ b1) {
    extern __shared__ char smem[];
    const uint32_t smem_base = smem_u32(smem);
    const int tid = threadIdx.x, wid = tid >> 5, lane = tid & 31;
    const int n0 = blockIdx.x * 128;
    const int m0 = blockIdx.y * 128;
    const int m_off = (wid & 3) * 32;     // 4 M-warps
    const int n_off = (wid >> 2) * 64;    // 2 N-warps

    const __nv_bfloat16* srcs[4] = {
        g_Xh  + (size_t)m0 * 512, g_Xl  + (size_t)m0 * 512,
        g_Wth + (size_t)n0 * 512, g_Wtl + (size_t)n0 * 512};

    auto prefetch = [&](int c, int buf) {
        const uint32_t sm0 = smem_base + buf * BUFB;
#pragma unroll
        for (int it = 0; it < 8; it++) {
            int t = it * 256 + tid;
            int s = t >> 9, r = (t >> 2) & 127, q = t & 3;
            cp_async16(sm0 + s * TILE_B + r * ASTRIDE + q * 16,
                       srcs[s] + (size_t)r * 512 + c * BK + q * 8);
        }
    };

    float acc[2][8][4];
#pragma unroll
    for (int i = 0; i < 2; i++)
#pragma unroll
        for (int j = 0; j < 8; j++)
#pragma unroll
            for (int k = 0; k < 4; k++) acc[i][j][k] = 0.f;

    // per-lane ldmatrix address components
    const int grp = lane >> 3, ln8 = lane & 7;
    const int a_row = (grp & 1) * 8 + ln8;     // + m base
    const int a_kB  = (grp >> 1) * 16;         // k byte offset within step
    const int b_row = ((grp >> 1) & 1) * 8 + ln8;
    const int b_kB  = (grp & 1) * 16;

    prefetch(0, 0);
    asm volatile("cp.async.commit_group;" ::: "memory");

    for (int c = 0; c < 16; c++) {
        const int buf = c & 1;
        if (c + 1 < 16) {
            prefetch(c + 1, buf ^ 1);
            asm volatile("cp.async.commit_group;" ::: "memory");
            asm volatile("cp.async.wait_group 1;" ::: "memory");
        } else {
            asm volatile("cp.async.wait_group 0;" ::: "memory");
        }
        __syncthreads();

        const uint32_t base = smem_base + buf * BUFB;
#pragma unroll
        for (int p = 0; p < 3; p++) {                 // hh, hl, lh
            const uint32_t Ab = base + ((p == 2) ? TILE_B : 0);
            const uint32_t Bb = base + ((p == 1) ? 3 : 2) * TILE_B;
#pragma unroll
            for (int ks = 0; ks < 2; ks++) {
                const int kB = ks * 32;               // 16 bf16 = 32B
                uint32_t a[2][4];
#pragma unroll
                for (int fm = 0; fm < 2; fm++)
                    ldsm_x4(a[fm], Ab + (m_off + fm * 16 + a_row) * ASTRIDE
                                      + kB + a_kB);
                uint32_t b[4][4];
#pragma unroll
                for (int fp = 0; fp < 4; fp++)
                    ldsm_x4(b[fp], Bb + (n_off + fp * 16 + b_row) * ASTRIDE
                                      + kB + b_kB);
#pragma unroll
                for (int fm = 0; fm < 2; fm++)
#pragma unroll
                    for (int fp = 0; fp < 4; fp++) {
                        mma_bf16(acc[fm][2 * fp + 0], a[fm], b[fp][0], b[fp][1]);
                        mma_bf16(acc[fm][2 * fp + 1], a[fm], b[fp][2], b[fp][3]);
                    }
            }
        }
        __syncthreads();
    }

    // epilogue
    const int r0 = lane >> 2, cc = (lane & 3) * 2;
#pragma unroll
    for (int fm = 0; fm < 2; fm++) {
        const int mrow = m0 + m_off + fm * 16 + r0;
#pragma unroll
        for (int fn = 0; fn < 8; fn++) {
            const int gcol = n0 + n_off + fn * 8 + cc;
            const float* a4 = acc[fm][fn];
            if (n0 < 512) {
                float2 bb = *(const float2*)&b1[gcol];
                *(float2*)&g_AB[(size_t)mrow * 512 + gcol] =
                    make_float2(a4[0] + bb.x, a4[1] + bb.y);
                *(float2*)&g_AB[(size_t)(mrow + 8) * 512 + gcol] =
                    make_float2(a4[2] + bb.x, a4[3] + bb.y);
            } else {
                *(float2*)&g_C[(size_t)mrow * 512 + gcol - 512] =
                    make_float2(a4[0], a4[1]);
                *(float2*)&g_C[(size_t)(mrow + 8) * 512 + gcol - 512] =
                    make_float2(a4[2], a4[3]);
            }
        }
    }
}

// ---------------- kernel 2: per-row dot products u, v ----------------------
__global__ void rowdot_kernel(const float* __restrict__ W2) {
    const int gw = (blockIdx.x * blockDim.x + threadIdx.x) >> 5;
    const int lane = threadIdx.x & 31;
    if (gw >= M_) return;
    const float* ab = &g_AB[(size_t)gw * D_];
    const float* cc = &g_C[(size_t)gw * D_];
    float su = 0.f, sv = 0.f;
#pragma unroll 4
    for (int h = lane; h < D_; h += 32) {
        float w = W2[h];
        su = fmaf(ab[h], w, su);
        sv = fmaf(cc[h], w, sv);
    }
#pragma unroll
    for (int o = 16; o > 0; o >>= 1) {
        su += __shfl_xor_sync(0xffffffffu, su, o);
        sv += __shfl_xor_sync(0xffffffffu, sv, o);
    }
    if (lane == 0) { g_u[gw] = su; g_v[gw] = sv; }
}

// ---------------- kernel 3: pairwise |.| reduction + fused softmax-CE ------
__global__ void pairwise_kernel(const float* __restrict__ W2,
                                const float* __restrict__ b2,
                                const int* __restrict__ order) {
    __shared__ float Cs[16][D_];
    __shared__ float rowbuf[ITILE][L_];
    __shared__ int   ord[L_];
    __shared__ float vsh[L_];
    __shared__ float wpart[ITILE];

    const int b  = blockIdx.y;
    const int i0 = blockIdx.x * ITILE;
    const int tid = threadIdx.x;
    const int warp = tid >> 5;
    const int lane = tid & 31;
    const int i = i0 + warp;

    if (tid < L_) {
        ord[tid] = order[b * L_ + tid];
        vsh[tid] = g_v[b * L_ + tid];
    }

    const float* abrow = &g_AB[(size_t)(b * L_ + i) * D_];
    float4 ab4[4], w24[4];
#pragma unroll
    for (int t = 0; t < 4; t++) {
        ab4[t] = *(const float4*)&abrow[t * 128 + lane * 4];
        w24[t] = *(const float4*)&W2[t * 128 + lane * 4];
    }
    const float u   = g_u[b * L_ + i];
    const float b2v = b2[0];

    for (int jc = 0; jc < L_; jc += 16) {
        __syncthreads();
        for (int t = tid; t < 16 * 128; t += 256) {
            int r = t >> 7, c4 = t & 127;
            ((float4*)&Cs[r][0])[c4] =
                ((const float4*)&g_C[(size_t)(b * L_ + jc + r) * D_])[c4];
        }
        __syncthreads();

        for (int jj = 0; jj < 16; jj++) {
            float acc0 = 0.f, acc1 = 0.f;
#pragma unroll
            for (int t = 0; t < 4; t++) {
                float4 cv = *(const float4*)&Cs[jj][t * 128 + lane * 4];
                float s;
                s = ab4[t].x + cv.x; acc0 = fmaf(fabsf(s), w24[t].x, acc0);
                s = ab4[t].y + cv.y; acc1 = fmaf(fabsf(s), w24[t].y, acc1);
                s = ab4[t].z + cv.z; acc0 = fmaf(fabsf(s), w24[t].z, acc0);
                s = ab4[t].w + cv.w; acc1 = fmaf(fabsf(s), w24[t].w, acc1);
            }
            float acc = acc0 + acc1;
#pragma unroll
            for (int o = 16; o > 0; o >>= 1)
                acc += __shfl_xor_sync(0xffffffffu, acc, o);
            if (lane == 0) {
                int j = jc + jj;
                rowbuf[warp][j] = 0.55f * (u + vsh[j]) + 0.45f * acc + b2v;
            }
        }
    }
    __syncthreads();

    float l0 = rowbuf[warp][lane];
    float l1 = rowbuf[warp][lane + 32];
    float l2 = rowbuf[warp][lane + 64];
    float m = fmaxf(l0, fmaxf(l1, l2));
#pragma unroll
    for (int o = 16; o > 0; o >>= 1)
        m = fmaxf(m, __shfl_xor_sync(0xffffffffu, m, o));
    float s = expf(l0 - m) + expf(l1 - m) + expf(l2 - m);
#pragma unroll
    for (int o = 16; o > 0; o >>= 1)
        s += __shfl_xor_sync(0xffffffffu, s, o);
    float lse = m + logf(s);

    int oi = ord[i];
    int o0 = ord[lane], o1 = ord[lane + 32], o2 = ord[lane + 64];
    unsigned t0 = __ballot_sync(0xffffffffu, o0 == oi + 1);
    unsigned t1 = __ballot_sync(0xffffffffu, o1 == oi + 1);
    unsigned t2 = __ballot_sync(0xffffffffu, o2 == oi + 1);
    int tgt = t0 ? (__ffs(t0) - 1)
                 : (t1 ? (31 + __ffs(t1)) : (t2 ? (63 + __ffs(t2)) : 0));

    int mx = max(o0, max(o1, o2));
#pragma unroll
    for (int o = 16; o > 0; o >>= 1)
        mx = max(mx, __shfl_xor_sync(0xffffffffu, mx, o));
    unsigned M0 = __ballot_sync(0xffffffffu, o0 == mx);
    unsigned M1 = __ballot_sync(0xffffffffu, o1 == mx);
    unsigned M2 = __ballot_sync(0xffffffffu, o2 == mx);
    int last = M0 ? (__ffs(M0) - 1) : (M1 ? (31 + __ffs(M1)) : (63 + __ffs(M2)));

    float contrib = (i == last) ? 0.f : (lse - rowbuf[warp][tgt]);
    if (lane == 0) wpart[warp] = contrib;
    __syncthreads();
    if (tid == 0) {
        float ssum = 0.f;
#pragma unroll
        for (int w = 0; w < ITILE; w++) ssum += wpart[w];
        g_partial[b * (L_ / ITILE) + blockIdx.x] = ssum;
    }
}

// ---------------- kernel 4: deterministic final reduction ------------------
__global__ void finalize_kernel(float* __restrict__ out) {
    __shared__ float sh[NPART];
    int t = threadIdx.x;
    if (t < NPART) sh[t] = g_partial[t];
    __syncthreads();
    if (t == 0) {
        float s = 0.f;
        for (int k = 0; k < NPART; k++) s += sh[k];
        out[0] = s * (1.0f / (16.0f * 95.0f));
    }
}

// ---------------- launcher --------------------------------------------------
extern "C" void kernel_launch(void* const* d_in, const int* in_sizes, int n_in,
                              void* d_out, int out_size) {
    const float* X    = (const float*)d_in[0];
    const float* W1   = (const float*)d_in[1];
    const float* b1   = (const float*)d_in[2];
    const float* W2   = (const float*)d_in[3];
    const float* b2   = (const float*)d_in[4];
    const int*   order = (const int*)d_in[6];

    static bool attr_set = false;
    if (!attr_set) {
        cudaFuncSetAttribute(gemm_mma_kernel,
                             cudaFuncAttributeMaxDynamicSharedMemorySize, GEMM_SMEM);
        attr_set = true;
    }

    convert_kernel<<<1280, 256>>>(X, W1);
    gemm_mma_kernel<<<dim3(8, 12), 256, GEMM_SMEM>>>(b1);
    rowdot_kernel<<<192, 256>>>(W2);
    pairwise_kernel<<<dim3(L_ / ITILE, B_), 256>>>(W2, b2, order);
    finalize_kernel<<<1, 256>>>((float*)d_out);
}

// round 7
// speedup vs baseline: 1.5379x; 1.0031x over previous
#include <cuda_runtime.h>
#include <cuda_bf16.h>
#include <cstdint>

#define B_  16
#define L_  96
#define D_  512
#define M_  (B_ * L_)
#define ITILE 8
#define NPART (B_ * (L_ / ITILE))

// ---------------- device scratch ------------------------------------------
__device__ float g_AB[M_ * D_];
__device__ float g_C[M_ * D_];
__device__ float g_u[M_];
__device__ float g_v[M_];
__device__ float g_partial[NPART];
__device__ __nv_bfloat16 g_Xh[M_ * D_];
__device__ __nv_bfloat16 g_Xl[M_ * D_];
__device__ __nv_bfloat16 g_Wth[1024 * D_];   // W1 transposed: [n][k]
__device__ __nv_bfloat16 g_Wtl[1024 * D_];

// ---------------- helpers ---------------------------------------------------
__device__ __forceinline__ uint32_t smem_u32(const void* p) {
    uint32_t a;
    asm("{ .reg .u64 t; cvta.to.shared.u64 t, %1; cvt.u32.u64 %0, t; }"
        : "=r"(a) : "l"(p));
    return a;
}
__device__ __forceinline__ void ldsm_x4(uint32_t* r, uint32_t addr) {
    asm volatile("ldmatrix.sync.aligned.m8n8.x4.shared.b16 {%0,%1,%2,%3}, [%4];"
                 : "=r"(r[0]), "=r"(r[1]), "=r"(r[2]), "=r"(r[3]) : "r"(addr));
}
__device__ __forceinline__ void mma_bf16(float* c, const uint32_t* a,
                                         uint32_t b0, uint32_t b1) {
    asm volatile(
        "mma.sync.aligned.m16n8k16.row.col.f32.bf16.bf16.f32 "
        "{%0,%1,%2,%3}, {%4,%5,%6,%7}, {%8,%9}, {%0,%1,%2,%3};"
        : "+f"(c[0]), "+f"(c[1]), "+f"(c[2]), "+f"(c[3])
        : "r"(a[0]), "r"(a[1]), "r"(a[2]), "r"(a[3]), "r"(b0), "r"(b1));
}
__device__ __forceinline__ void cp_async16(uint32_t saddr, const void* gaddr) {
    asm volatile("cp.async.cg.shared.global [%0], [%1], 16;"
                 :: "r"(saddr), "l"(gaddr));
}

// ---------------- kernel A: convert/split X and W1 -------------------------
// blocks [0,768): X split.  blocks [768,1280): W1 transpose+split.
__global__ void convert_kernel(const float* __restrict__ X,
                               const float* __restrict__ W1) {
    const int tid = threadIdx.x;
    if (blockIdx.x < 768) {
        int idx = blockIdx.x * 256 + tid;         // over 196608 float4
        float4 v = ((const float4*)X)[idx];
        __nv_bfloat16 hx = __float2bfloat16(v.x), hy = __float2bfloat16(v.y);
        __nv_bfloat16 hz = __float2bfloat16(v.z), hw = __float2bfloat16(v.w);
        __nv_bfloat16 lx = __float2bfloat16(v.x - __bfloat162float(hx));
        __nv_bfloat16 ly = __float2bfloat16(v.y - __bfloat162float(hy));
        __nv_bfloat16 lz = __float2bfloat16(v.z - __bfloat162float(hz));
        __nv_bfloat16 lw = __float2bfloat16(v.w - __bfloat162float(hw));
        ((__nv_bfloat162*)g_Xh)[idx * 2 + 0] = __nv_bfloat162(hx, hy);
        ((__nv_bfloat162*)g_Xh)[idx * 2 + 1] = __nv_bfloat162(hz, hw);
        ((__nv_bfloat162*)g_Xl)[idx * 2 + 0] = __nv_bfloat162(lx, ly);
        ((__nv_bfloat162*)g_Xl)[idx * 2 + 1] = __nv_bfloat162(lz, lw);
    } else {
        __shared__ float t[32][33];
        const int wb = blockIdx.x - 768;          // 0..511
        const int p  = wb >> 8;                   // 0/1
        const int k0 = ((wb >> 4) & 15) * 32;
        const int n0 = (wb & 15) * 32;
        const int tx = tid & 31, ty = tid >> 5;   // (32, 8)
#pragma unroll
        for (int r = 0; r < 32; r += 8)
            t[ty + r][tx] = W1[(size_t)(p * 512 + k0 + ty + r) * 512 + n0 + tx];
        __syncthreads();
#pragma unroll
        for (int r = 0; r < 32; r += 8) {
            float v = t[tx][ty + r];
            __nv_bfloat16 h = __float2bfloat16(v);
            __nv_bfloat16 l = __float2bfloat16(v - __bfloat162float(h));
            size_t o = (size_t)(p * 512 + n0 + ty + r) * 512 + k0 + tx;
            g_Wth[o] = h;
            g_Wtl[o] = l;
        }
    }
}

// ---------------- kernel B: bf16-split GEMM via mma.sync --------------------
// out[m,n], m<1536, n<1024: n<512 -> g_AB (+b1), n>=512 -> g_C
#define BK 32
#define ASTRIDE 80                 // bytes per smem row (40 bf16)
#define TILE_B (128 * ASTRIDE)     // 10240
#define BUFB   (4 * TILE_B)        // Ah, Al, Bh, Bl
#define GEMM_SMEM (2 * BUFB)       // 81920

__global__ void __launch_bounds__(256, 1)
gemm_mma_kernel(const float* __restrict__ b1) {
    extern __shared__ char smem[];
    const uint32_t smem_base = smem_u32(smem);
    const int tid = threadIdx.x, wid = tid >> 5, lane = tid & 31;
    const int n0 = blockIdx.x * 128;
    const int m0 = blockIdx.y * 128;
    const int m_off = (wid & 3) * 32;     // 4 M-warps
    const int n_off = (wid >> 2) * 64;    // 2 N-warps

    const __nv_bfloat16* srcs[4] = {
        g_Xh  + (size_t)m0 * 512, g_Xl  + (size_t)m0 * 512,
        g_Wth + (size_t)n0 * 512, g_Wtl + (size_t)n0 * 512};

    auto prefetch = [&](int c, int buf) {
        const uint32_t sm0 = smem_base + buf * BUFB;
#pragma unroll
        for (int it = 0; it < 8; it++) {
            int t = it * 256 + tid;
            int s = t >> 9, r = (t >> 2) & 127, q = t & 3;
            cp_async16(sm0 + s * TILE_B + r * ASTRIDE + q * 16,
                       srcs[s] + (size_t)r * 512 + c * BK + q * 8);
        }
    };

    float acc[2][8][4];
#pragma unroll
    for (int i = 0; i < 2; i++)
#pragma unroll
        for (int j = 0; j < 8; j++)
#pragma unroll
            for (int k = 0; k < 4; k++) acc[i][j][k] = 0.f;

    // per-lane ldmatrix address components
    const int grp = lane >> 3, ln8 = lane & 7;
    const int a_row = (grp & 1) * 8 + ln8;     // + m base
    const int a_kB  = (grp >> 1) * 16;         // k byte offset within step
    const int b_row = ((grp >> 1) & 1) * 8 + ln8;
    const int b_kB  = (grp & 1) * 16;

    prefetch(0, 0);
    asm volatile("cp.async.commit_group;" ::: "memory");

    for (int c = 0; c < 16; c++) {
        const int buf = c & 1;
        if (c + 1 < 16) {
            prefetch(c + 1, buf ^ 1);
            asm volatile("cp.async.commit_group;" ::: "memory");
            asm volatile("cp.async.wait_group 1;" ::: "memory");
        } else {
            asm volatile("cp.async.wait_group 0;" ::: "memory");
        }
        __syncthreads();

        const uint32_t base = smem_base + buf * BUFB;
#pragma unroll
        for (int p = 0; p < 3; p++) {                 // hh, hl, lh
            const uint32_t Ab = base + ((p == 2) ? TILE_B : 0);
            const uint32_t Bb = base + ((p == 1) ? 3 : 2) * TILE_B;
#pragma unroll
            for (int ks = 0; ks < 2; ks++) {
                const int kB = ks * 32;               // 16 bf16 = 32B
                uint32_t a[2][4];
#pragma unroll
                for (int fm = 0; fm < 2; fm++)
                    ldsm_x4(a[fm], Ab + (m_off + fm * 16 + a_row) * ASTRIDE
                                      + kB + a_kB);
                uint32_t b[4][4];
#pragma unroll
                for (int fp = 0; fp < 4; fp++)
                    ldsm_x4(b[fp], Bb + (n_off + fp * 16 + b_row) * ASTRIDE
                                      + kB + b_kB);
#pragma unroll
                for (int fm = 0; fm < 2; fm++)
#pragma unroll
                    for (int fp = 0; fp < 4; fp++) {
                        mma_bf16(acc[fm][2 * fp + 0], a[fm], b[fp][0], b[fp][1]);
                        mma_bf16(acc[fm][2 * fp + 1], a[fm], b[fp][2], b[fp][3]);
                    }
            }
        }
        __syncthreads();
    }

    // epilogue
    const int r0 = lane >> 2, cc = (lane & 3) * 2;
#pragma unroll
    for (int fm = 0; fm < 2; fm++) {
        const int mrow = m0 + m_off + fm * 16 + r0;
#pragma unroll
        for (int fn = 0; fn < 8; fn++) {
            const int gcol = n0 + n_off + fn * 8 + cc;
            const float* a4 = acc[fm][fn];
            if (n0 < 512) {
                float2 bb = *(const float2*)&b1[gcol];
                *(float2*)&g_AB[(size_t)mrow * 512 + gcol] =
                    make_float2(a4[0] + bb.x, a4[1] + bb.y);
                *(float2*)&g_AB[(size_t)(mrow + 8) * 512 + gcol] =
                    make_float2(a4[2] + bb.x, a4[3] + bb.y);
            } else {
                *(float2*)&g_C[(size_t)mrow * 512 + gcol - 512] =
                    make_float2(a4[0], a4[1]);
                *(float2*)&g_C[(size_t)(mrow + 8) * 512 + gcol - 512] =
                    make_float2(a4[2], a4[3]);
            }
        }
    }
}

// ---------------- kernel 2: per-row dot products u, v ----------------------
__global__ void rowdot_kernel(const float* __restrict__ W2) {
    const int gw = (blockIdx.x * blockDim.x + threadIdx.x) >> 5;
    const int lane = threadIdx.x & 31;
    if (gw >= M_) return;
    const float* ab = &g_AB[(size_t)gw * D_];
    const float* cc = &g_C[(size_t)gw * D_];
    float su = 0.f, sv = 0.f;
#pragma unroll 4
    for (int h = lane; h < D_; h += 32) {
        float w = W2[h];
        su = fmaf(ab[h], w, su);
        sv = fmaf(cc[h], w, sv);
    }
#pragma unroll
    for (int o = 16; o > 0; o >>= 1) {
        su += __shfl_xor_sync(0xffffffffu, su, o);
        sv += __shfl_xor_sync(0xffffffffu, sv, o);
    }
    if (lane == 0) { g_u[gw] = su; g_v[gw] = sv; }
}

// ---------------- kernel 3: pairwise |.| reduction + fused softmax-CE ------
__global__ void pairwise_kernel(const float* __restrict__ W2,
                                const float* __restrict__ b2,
                                const int* __restrict__ order) {
    __shared__ float Cs[16][D_];
    __shared__ float rowbuf[ITILE][L_];
    __shared__ int   ord[L_];
    __shared__ float vsh[L_];
    __shared__ float wpart[ITILE];

    const int b  = blockIdx.y;
    const int i0 = blockIdx.x * ITILE;
    const int tid = threadIdx.x;
    const int warp = tid >> 5;
    const int lane = tid & 31;
    const int i = i0 + warp;

    if (tid < L_) {
        ord[tid] = order[b * L_ + tid];
        vsh[tid] = g_v[b * L_ + tid];
    }

    const float* abrow = &g_AB[(size_t)(b * L_ + i) * D_];
    float4 ab4[4], w24[4];
#pragma unroll
    for (int t = 0; t < 4; t++) {
        ab4[t] = *(const float4*)&abrow[t * 128 + lane * 4];
        w24[t] = *(const float4*)&W2[t * 128 + lane * 4];
    }
    const float u   = g_u[b * L_ + i];
    const float b2v = b2[0];

    for (int jc = 0; jc < L_; jc += 16) {
        __syncthreads();
        for (int t = tid; t < 16 * 128; t += 256) {
            int r = t >> 7, c4 = t & 127;
            ((float4*)&Cs[r][0])[c4] =
                ((const float4*)&g_C[(size_t)(b * L_ + jc + r) * D_])[c4];
        }
        __syncthreads();

        for (int jj = 0; jj < 16; jj++) {
            float acc0 = 0.f, acc1 = 0.f;
#pragma unroll
            for (int t = 0; t < 4; t++) {
                float4 cv = *(const float4*)&Cs[jj][t * 128 + lane * 4];
                float s;
                s = ab4[t].x + cv.x; acc0 = fmaf(fabsf(s), w24[t].x, acc0);
                s = ab4[t].y + cv.y; acc1 = fmaf(fabsf(s), w24[t].y, acc1);
                s = ab4[t].z + cv.z; acc0 = fmaf(fabsf(s), w24[t].z, acc0);
                s = ab4[t].w + cv.w; acc1 = fmaf(fabsf(s), w24[t].w, acc1);
            }
            float acc = acc0 + acc1;
#pragma unroll
            for (int o = 16; o > 0; o >>= 1)
                acc += __shfl_xor_sync(0xffffffffu, acc, o);
            if (lane == 0) {
                int j = jc + jj;
                rowbuf[warp][j] = 0.55f * (u + vsh[j]) + 0.45f * acc + b2v;
            }
        }
    }
    __syncthreads();

    float l0 = rowbuf[warp][lane];
    float l1 = rowbuf[warp][lane + 32];
    float l2 = rowbuf[warp][lane + 64];
    float m = fmaxf(l0, fmaxf(l1, l2));
#pragma unroll
    for (int o = 16; o > 0; o >>= 1)
        m = fmaxf(m, __shfl_xor_sync(0xffffffffu, m, o));
    float s = expf(l0 - m) + expf(l1 - m) + expf(l2 - m);
#pragma unroll
    for (int o = 16; o > 0; o >>= 1)
        s += __shfl_xor_sync(0xffffffffu, s, o);
    float lse = m + logf(s);

    int oi = ord[i];
    int o0 = ord[lane], o1 = ord[lane + 32], o2 = ord[lane + 64];
    unsigned t0 = __ballot_sync(0xffffffffu, o0 == oi + 1);
    unsigned t1 = __ballot_sync(0xffffffffu, o1 == oi + 1);
    unsigned t2 = __ballot_sync(0xffffffffu, o2 == oi + 1);
    int tgt = t0 ? (__ffs(t0) - 1)
                 : (t1 ? (31 + __ffs(t1)) : (t2 ? (63 + __ffs(t2)) : 0));

    int mx = max(o0, max(o1, o2));
#pragma unroll
    for (int o = 16; o > 0; o >>= 1)
        mx = max(mx, __shfl_xor_sync(0xffffffffu, mx, o));
    unsigned M0 = __ballot_sync(0xffffffffu, o0 == mx);
    unsigned M1 = __ballot_sync(0xffffffffu, o1 == mx);
    unsigned M2 = __ballot_sync(0xffffffffu, o2 == mx);
    int last = M0 ? (__ffs(M0) - 1) : (M1 ? (31 + __ffs(M1)) : (63 + __ffs(M2)));

    float contrib = (i == last) ? 0.f : (lse - rowbuf[warp][tgt]);
    if (lane == 0) wpart[warp] = contrib;
    __syncthreads();
    if (tid == 0) {
        float ssum = 0.f;
#pragma unroll
        for (int w = 0; w < ITILE; w++) ssum += wpart[w];
        g_partial[b * (L_ / ITILE) + blockIdx.x] = ssum;
    }
}

// ---------------- kernel 4: deterministic final reduction ------------------
__global__ void finalize_kernel(float* __restrict__ out) {
    __shared__ float sh[NPART];
    int t = threadIdx.x;
    if (t < NPART) sh[t] = g_partial[t];
    __syncthreads();
    if (t == 0) {
        float s = 0.f;
        for (int k = 0; k < NPART; k++) s += sh[k];
        out[0] = s * (1.0f / (16.0f * 95.0f));
    }
}

// ---------------- launcher --------------------------------------------------
extern "C" void kernel_launch(void* const* d_in, const int* in_sizes, int n_in,
                              void* d_out, int out_size) {
    const float* X    = (const float*)d_in[0];
    const float* W1   = (const float*)d_in[1];
    const float* b1   = (const float*)d_in[2];
    const float* W2   = (const float*)d_in[3];
    const float* b2   = (const float*)d_in[4];
    const int*   order = (const int*)d_in[6];

    static bool attr_set = false;
    if (!attr_set) {
        cudaFuncSetAttribute(gemm_mma_kernel,
                             cudaFuncAttributeMaxDynamicSharedMemorySize, GEMM_SMEM);
        attr_set = true;
    }

    convert_kernel<<<1280, 256>>>(X, W1);
    gemm_mma_kernel<<<dim3(8, 12), 256, GEMM_SMEM>>>(b1);
    rowdot_kernel<<<192, 256>>>(W2);
    pairwise_kernel<<<dim3(L_ / ITILE, B_), 256>>>(W2, b2, order);
    finalize_kernel<<<1, 256>>>((float*)d_out);
}

// round 8
// speedup vs baseline: 1.8050x; 1.1737x over previous
#include <cuda_runtime.h>
#include <cuda_bf16.h>
#include <cstdint>

#define B_  16
#define L_  96
#define D_  512
#define M_  (B_ * L_)
#define NPART 192                      // 12 x 16 CE blocks
#define PSTRIDE (B_ * L_ * L_)         // 147456 per h-slice

// ---------------- device scratch ------------------------------------------
__device__ float g_AB2[M_ * D_];       // [b][hp][i]: (a+b1)*|w2|, h permuted
__device__ float g_C2[M_ * D_];        // [b][hp][j]: c*|w2|, h permuted
__device__ float g_P[4 * PSTRIDE];     // abs partial sums per h-slice
__device__ float g_v4[4 * M_];         // v partials per h-slice
__device__ float g_partial[NPART];
__device__ int   g_perm[D_];           // source h -> permuted row
__device__ float g_w2a[D_];            // |w2[h]| (source-indexed)
__device__ int   g_Hpos;               // count of w2 >= 0
__device__ __nv_bfloat16 g_Xh[M_ * D_];
__device__ __nv_bfloat16 g_Xl[M_ * D_];
__device__ __nv_bfloat16 g_Wth[1024 * D_];
__device__ __nv_bfloat16 g_Wtl[1024 * D_];

// ---------------- helpers ---------------------------------------------------
__device__ __forceinline__ uint32_t smem_u32(const void* p) {
    uint32_t a;
    asm("{ .reg .u64 t; cvta.to.shared.u64 t, %1; cvt.u32.u64 %0, t; }"
        : "=r"(a) : "l"(p));
    return a;
}
__device__ __forceinline__ void ldsm_x4(uint32_t* r, uint32_t addr) {
    asm volatile("ldmatrix.sync.aligned.m8n8.x4.shared.b16 {%0,%1,%2,%3}, [%4];"
                 : "=r"(r[0]), "=r"(r[1]), "=r"(r[2]), "=r"(r[3]) : "r"(addr));
}
__device__ __forceinline__ void mma_bf16(float* c, const uint32_t* a,
                                         uint32_t b0, uint32_t b1) {
    asm volatile(
        "mma.sync.aligned.m16n8k16.row.col.f32.bf16.bf16.f32 "
        "{%0,%1,%2,%3}, {%4,%5,%6,%7}, {%8,%9}, {%0,%1,%2,%3};"
        : "+f"(c[0]), "+f"(c[1]), "+f"(c[2]), "+f"(c[3])
        : "r"(a[0]), "r"(a[1]), "r"(a[2]), "r"(a[3]), "r"(b0), "r"(b1));
}
__device__ __forceinline__ void cp_async16(uint32_t saddr, const void* gaddr) {
    asm volatile("cp.async.cg.shared.global [%0], [%1], 16;"
                 :: "r"(saddr), "l"(gaddr));
}

// ---------------- kernel A: convert/split X, W1 + sign-partition perm ------
// block 0: perm from W2. blocks [1,385): X split. blocks [385,897): W1 T+split
__global__ void __launch_bounds__(512)
convert_kernel(const float* __restrict__ X, const float* __restrict__ W1,
               const float* __restrict__ W2) {
    const int tid = threadIdx.x;
    const int bx = blockIdx.x;
    if (bx == 0) {
        // deterministic stable partition of h by sign(w2)
        __shared__ int wcnt[16], wpre[17];
        const int lane = tid & 31, w = tid >> 5;
        float v = W2[tid];
        bool pos = (v >= 0.f);
        unsigned mset = __ballot_sync(0xffffffffu, pos);
        int lpre = __popc(mset & ((1u << lane) - 1u));
        if (lane == 0) wcnt[w] = __popc(mset);
        __syncthreads();
        if (tid == 0) {
            int s = 0;
#pragma unroll
            for (int k = 0; k < 16; k++) { wpre[k] = s; s += wcnt[k]; }
            wpre[16] = s;
        }
        __syncthreads();
        int Hp = wpre[16];
        int posrank = wpre[w] + lpre;
        g_perm[tid] = pos ? posrank : (Hp + tid - posrank);
        g_w2a[tid] = fabsf(v);
        if (tid == 0) g_Hpos = Hp;
    } else if (bx < 385) {
        int idx = (bx - 1) * 512 + tid;          // over 196608 float4
        float4 v = ((const float4*)X)[idx];
        __nv_bfloat16 hx = __float2bfloat16(v.x), hy = __float2bfloat16(v.y);
        __nv_bfloat16 hz = __float2bfloat16(v.z), hw = __float2bfloat16(v.w);
        __nv_bfloat16 lx = __float2bfloat16(v.x - __bfloat162float(hx));
        __nv_bfloat16 ly = __float2bfloat16(v.y - __bfloat162float(hy));
        __nv_bfloat16 lz = __float2bfloat16(v.z - __bfloat162float(hz));
        __nv_bfloat16 lw = __float2bfloat16(v.w - __bfloat162float(hw));
        ((__nv_bfloat162*)g_Xh)[idx * 2 + 0] = __nv_bfloat162(hx, hy);
        ((__nv_bfloat162*)g_Xh)[idx * 2 + 1] = __nv_bfloat162(hz, hw);
        ((__nv_bfloat162*)g_Xl)[idx * 2 + 0] = __nv_bfloat162(lx, ly);
        ((__nv_bfloat162*)g_Xl)[idx * 2 + 1] = __nv_bfloat162(lz, lw);
    } else {
        __shared__ float t[32][33];
        const int wb = bx - 385;                 // 0..511
        const int p  = wb >> 8;
        const int k0 = ((wb >> 4) & 15) * 32;
        const int n0 = (wb & 15) * 32;
        const int tx = tid & 31, ty = tid >> 5;  // (32,16)
#pragma unroll
        for (int r = 0; r < 32; r += 16)
            t[ty + r][tx] = W1[(size_t)(p * 512 + k0 + ty + r) * 512 + n0 + tx];
        __syncthreads();
#pragma unroll
        for (int r = 0; r < 32; r += 16) {
            float v = t[tx][ty + r];
            __nv_bfloat16 h = __float2bfloat16(v);
            __nv_bfloat16 l = __float2bfloat16(v - __bfloat162float(h));
            size_t o = (size_t)(p * 512 + n0 + ty + r) * 512 + k0 + tx;
            g_Wth[o] = h;
            g_Wtl[o] = l;
        }
    }
}

// ---------------- kernel B: bf16-split GEMM via mma.sync --------------------
// epilogue writes permuted/scaled AB2, C2 directly.
#define BK 32
#define ASTRIDE 80
#define TILE_B (128 * ASTRIDE)
#define BUFB   (4 * TILE_B)
#define GEMM_SMEM (2 * BUFB)

__global__ void __launch_bounds__(256, 1)
gemm_mma_kernel(const float* __restrict__ b1) {
    extern __shared__ char smem[];
    const uint32_t smem_base = smem_u32(smem);
    const int tid = threadIdx.x, wid = tid >> 5, lane = tid & 31;
    const int n0 = blockIdx.x * 128;
    const int m0 = blockIdx.y * 128;
    const int m_off = (wid & 3) * 32;
    const int n_off = (wid >> 2) * 64;

    const __nv_bfloat16* srcs[4] = {
        g_Xh  + (size_t)m0 * 512, g_Xl  + (size_t)m0 * 512,
        g_Wth + (size_t)n0 * 512, g_Wtl + (size_t)n0 * 512};

    auto prefetch = [&](int c, int buf) {
        const uint32_t sm0 = smem_base + buf * BUFB;
#pragma unroll
        for (int it = 0; it < 8; it++) {
            int t = it * 256 + tid;
            int s = t >> 9, r = (t >> 2) & 127, q = t & 3;
            cp_async16(sm0 + s * TILE_B + r * ASTRIDE + q * 16,
                       srcs[s] + (size_t)r * 512 + c * BK + q * 8);
        }
    };

    float acc[2][8][4];
#pragma unroll
    for (int i = 0; i < 2; i++)
#pragma unroll
        for (int j = 0; j < 8; j++)
#pragma unroll
            for (int k = 0; k < 4; k++) acc[i][j][k] = 0.f;

    const int grp = lane >> 3, ln8 = lane & 7;
    const int a_row = (grp & 1) * 8 + ln8;
    const int a_kB  = (grp >> 1) * 16;
    const int b_row = ((grp >> 1) & 1) * 8 + ln8;
    const int b_kB  = (grp & 1) * 16;

    prefetch(0, 0);
    asm volatile("cp.async.commit_group;" ::: "memory");

    for (int c = 0; c < 16; c++) {
        const int buf = c & 1;
        if (c + 1 < 16) {
            prefetch(c + 1, buf ^ 1);
            asm volatile("cp.async.commit_group;" ::: "memory");
            asm volatile("cp.async.wait_group 1;" ::: "memory");
        } else {
            asm volatile("cp.async.wait_group 0;" ::: "memory");
        }
        __syncthreads();

        const uint32_t base = smem_base + buf * BUFB;
#pragma unroll
        for (int p = 0; p < 3; p++) {
            const uint32_t Ab = base + ((p == 2) ? TILE_B : 0);
            const uint32_t Bb = base + ((p == 1) ? 3 : 2) * TILE_B;
#pragma unroll
            for (int ks = 0; ks < 2; ks++) {
                const int kB = ks * 32;
                uint32_t a[2][4];
#pragma unroll
                for (int fm = 0; fm < 2; fm++)
                    ldsm_x4(a[fm], Ab + (m_off + fm * 16 + a_row) * ASTRIDE
                                      + kB + a_kB);
                uint32_t b[4][4];
#pragma unroll
                for (int fp = 0; fp < 4; fp++)
                    ldsm_x4(b[fp], Bb + (n_off + fp * 16 + b_row) * ASTRIDE
                                      + kB + b_kB);
#pragma unroll
                for (int fm = 0; fm < 2; fm++)
#pragma unroll
                    for (int fp = 0; fp < 4; fp++) {
                        mma_bf16(acc[fm][2 * fp + 0], a[fm], b[fp][0], b[fp][1]);
                        mma_bf16(acc[fm][2 * fp + 1], a[fm], b[fp][2], b[fp][3]);
                    }
            }
        }
        __syncthreads();
    }

    // epilogue: scatter into permuted/scaled h-major layout
    const int r0 = lane >> 2, cc = (lane & 3) * 2;
#pragma unroll
    for (int fm = 0; fm < 2; fm++) {
        const int mr0 = m0 + m_off + fm * 16 + r0;
        const int mr1 = mr0 + 8;
        const int b0r = mr0 / 96, i0r = mr0 - b0r * 96;
        const int b1r = mr1 / 96, i1r = mr1 - b1r * 96;
#pragma unroll
        for (int fn = 0; fn < 8; fn++) {
            const int gc = n0 + n_off + fn * 8 + cc;
            const float* a4 = acc[fm][fn];
#pragma unroll
            for (int e = 0; e < 2; e++) {
                const int n = gc + e;
                const bool isA = (n < 512);
                const int h = isA ? n : (n - 512);
                const int hp = g_perm[h];
                const float sc = g_w2a[h];
                const float add = isA ? b1[n] : 0.f;
                float* dst = isA ? g_AB2 : g_C2;
                dst[((size_t)(b0r * 512 + hp)) * 96 + i0r] = (a4[e]     + add) * sc;
                dst[((size_t)(b1r * 512 + hp)) * 96 + i1r] = (a4[2 + e] + add) * sc;
            }
        }
    }
}

// ---------------- kernel C: v partials (u and b2 cancel in softmax) --------
__global__ void rowdot_kernel() {
    const int s = blockIdx.x, b = blockIdx.y;        // (4, 16)
    const int i = threadIdx.x;                       // 96
    const int bnd = min(max(g_Hpos - s * 128, 0), 128);
    const float* C = g_C2 + ((size_t)(b * 512 + s * 128)) * 96 + i;
    float v = 0.f;
    int h = 0;
#pragma unroll 4
    for (; h < bnd; h++) v += C[(size_t)h * 96];
#pragma unroll 4
    for (; h < 128; h++) v -= C[(size_t)h * 96];
    g_v4[s * M_ + b * 96 + i] = v;
}

// ---------------- kernel D: pairwise abs-sum, register-tiled ---------------
// grid (4 h-slices, 4 ij-tiles, 16 b); block 256 = 16x16; 3x3 per thread.
__global__ void __launch_bounds__(256)
pairwise_kernel() {
    __shared__ __align__(16) float As[128][48];
    __shared__ __align__(16) float Cs[128][48];

    const int hs = blockIdx.x;
    const int i0 = (blockIdx.y >> 1) * 48;
    const int j0 = (blockIdx.y & 1) * 48;
    const int b  = blockIdx.z;
    const int tid = threadIdx.x;
    const int il = 3 * (tid >> 4);
    const int jl = 3 * (tid & 15);

    // load 128x48 slices (each thread: 6 float4 per array)
    {
        const int h = tid >> 1, q0 = (tid & 1) * 6;
        const float4* sa = (const float4*)(g_AB2 +
            ((size_t)(b * 512 + hs * 128 + h)) * 96 + i0);
        const float4* sc = (const float4*)(g_C2 +
            ((size_t)(b * 512 + hs * 128 + h)) * 96 + j0);
        float4* da = (float4*)&As[h][0];
        float4* dc = (float4*)&Cs[h][0];
#pragma unroll
        for (int q = 0; q < 6; q++) {
            da[q0 + q] = sa[q0 + q];
            dc[q0 + q] = sc[q0 + q];
        }
    }
    __syncthreads();

    const int bnd = min(max(g_Hpos - hs * 128, 0), 128);
    float aP[3][3] = {{0.f}}, aN[3][3] = {{0.f}};
    const float* Ab = &As[0][il];
    const float* Cb = &Cs[0][jl];

    int h = 0;
#pragma unroll 4
    for (; h < bnd; h++) {
        float a0 = Ab[h * 48 + 0], a1 = Ab[h * 48 + 1], a2 = Ab[h * 48 + 2];
        float c0 = Cb[h * 48 + 0], c1 = Cb[h * 48 + 1], c2 = Cb[h * 48 + 2];
        aP[0][0] += fabsf(a0 + c0); aP[0][1] += fabsf(a0 + c1); aP[0][2] += fabsf(a0 + c2);
        aP[1][0] += fabsf(a1 + c0); aP[1][1] += fabsf(a1 + c1); aP[1][2] += fabsf(a1 + c2);
        aP[2][0] += fabsf(a2 + c0); aP[2][1] += fabsf(a2 + c1); aP[2][2] += fabsf(a2 + c2);
    }
#pragma unroll 4
    for (; h < 128; h++) {
        float a0 = Ab[h * 48 + 0], a1 = Ab[h * 48 + 1], a2 = Ab[h * 48 + 2];
        float c0 = Cb[h * 48 + 0], c1 = Cb[h * 48 + 1], c2 = Cb[h * 48 + 2];
        aN[0][0] += fabsf(a0 + c0); aN[0][1] += fabsf(a0 + c1); aN[0][2] += fabsf(a0 + c2);
        aN[1][0] += fabsf(a1 + c0); aN[1][1] += fabsf(a1 + c1); aN[1][2] += fabsf(a1 + c2);
        aN[2][0] += fabsf(a2 + c0); aN[2][1] += fabsf(a2 + c1); aN[2][2] += fabsf(a2 + c2);
    }

    float* P = g_P + (size_t)hs * PSTRIDE + ((size_t)b * 96) * 96;
#pragma unroll
    for (int r = 0; r < 3; r++)
#pragma unroll
        for (int c = 0; c < 3; c++)
            P[(size_t)(i0 + il + r) * 96 + (j0 + jl + c)] = aP[r][c] - aN[r][c];
}

// ---------------- kernel E: fused softmax-CE --------------------------------
__global__ void ce_kernel(const int* __restrict__ order) {
    __shared__ int   ord[96];
    __shared__ float vsh[96];
    __shared__ float rowbuf[8][96];
    __shared__ float wpart[8];

    const int b = blockIdx.y, tid = threadIdx.x;
    const int warp = tid >> 5, lane = tid & 31;
    const int i = blockIdx.x * 8 + warp;

    if (tid < 96) {
        ord[tid] = order[b * 96 + tid];
        vsh[tid] = g_v4[0 * M_ + b * 96 + tid] + g_v4[1 * M_ + b * 96 + tid]
                 + g_v4[2 * M_ + b * 96 + tid] + g_v4[3 * M_ + b * 96 + tid];
    }
    __syncthreads();

    const size_t ro = ((size_t)b * 96 + i) * 96;
    float lg[3];
#pragma unroll
    for (int r = 0; r < 3; r++) {
        int j = lane + r * 32;
        float P = g_P[ro + j] + g_P[PSTRIDE + ro + j]
                + g_P[2 * PSTRIDE + ro + j] + g_P[3 * PSTRIDE + ro + j];
        lg[r] = 0.55f * vsh[j] + 0.45f * P;
        rowbuf[warp][j] = lg[r];
    }

    float m = fmaxf(lg[0], fmaxf(lg[1], lg[2]));
#pragma unroll
    for (int o = 16; o > 0; o >>= 1)
        m = fmaxf(m, __shfl_xor_sync(0xffffffffu, m, o));
    float s = expf(lg[0] - m) + expf(lg[1] - m) + expf(lg[2] - m);
#pragma unroll
    for (int o = 16; o > 0; o >>= 1)
        s += __shfl_xor_sync(0xffffffffu, s, o);
    float lse = m + logf(s);

    int oi = ord[i];
    int o0 = ord[lane], o1 = ord[lane + 32], o2 = ord[lane + 64];
    unsigned t0 = __ballot_sync(0xffffffffu, o0 == oi + 1);
    unsigned t1 = __ballot_sync(0xffffffffu, o1 == oi + 1);
    unsigned t2 = __ballot_sync(0xffffffffu, o2 == oi + 1);
    int tgt = t0 ? (__ffs(t0) - 1)
                 : (t1 ? (31 + __ffs(t1)) : (t2 ? (63 + __ffs(t2)) : 0));

    int mx = max(o0, max(o1, o2));
#pragma unroll
    for (int o = 16; o > 0; o >>= 1)
        mx = max(mx, __shfl_xor_sync(0xffffffffu, mx, o));
    unsigned M0 = __ballot_sync(0xffffffffu, o0 == mx);
    unsigned M1 = __ballot_sync(0xffffffffu, o1 == mx);
    unsigned M2 = __ballot_sync(0xffffffffu, o2 == mx);
    int last = M0 ? (__ffs(M0) - 1) : (M1 ? (31 + __ffs(M1)) : (63 + __ffs(M2)));

    float contrib = (i == last) ? 0.f : (lse - rowbuf[warp][tgt]);
    if (lane == 0) wpart[warp] = contrib;
    __syncthreads();
    if (tid == 0) {
        float ssum = 0.f;
#pragma unroll
        for (int w = 0; w < 8; w++) ssum += wpart[w];
        g_partial[b * 12 + blockIdx.x] = ssum;
    }
}

// ---------------- kernel F: parallel final reduction ------------------------
__global__ void finalize_kernel(float* __restrict__ out) {
    __shared__ float wsum[8];
    const int t = threadIdx.x, lane = t & 31, w = t >> 5;
    float v = (t < NPART) ? g_partial[t] : 0.f;
#pragma unroll
    for (int o = 16; o > 0; o >>= 1)
        v += __shfl_xor_sync(0xffffffffu, v, o);
    if (lane == 0) wsum[w] = v;
    __syncthreads();
    if (t == 0) {
        float s = 0.f;
#pragma unroll
        for (int k = 0; k < 8; k++) s += wsum[k];
        out[0] = s * (1.0f / (16.0f * 95.0f));
    }
}

// ---------------- launcher --------------------------------------------------
extern "C" void kernel_launch(void* const* d_in, const int* in_sizes, int n_in,
                              void* d_out, int out_size) {
    const float* X    = (const float*)d_in[0];
    const float* W1   = (const float*)d_in[1];
    const float* b1   = (const float*)d_in[2];
    const float* W2   = (const float*)d_in[3];
    const int*   order = (const int*)d_in[6];

    static bool attr_set = false;
    if (!attr_set) {
        cudaFuncSetAttribute(gemm_mma_kernel,
                             cudaFuncAttributeMaxDynamicSharedMemorySize, GEMM_SMEM);
        attr_set = true;
    }

    convert_kernel<<<897, 512>>>(X, W1, W2);
    gemm_mma_kernel<<<dim3(8, 12), 256, GEMM_SMEM>>>(b1);
    rowdot_kernel<<<dim3(4, 16), 96>>>();
    pairwise_kernel<<<dim3(4, 4, 16), 256>>>();
    ce_kernel<<<dim3(12, 16), 256>>>(order);
    finalize_kernel<<<1, 256>>>((float*)d_out);
}

// round 9
// speedup vs baseline: 2.3202x; 1.2854x over previous
#include <cuda_runtime.h>
#include <cuda_bf16.h>
#include <cstdint>

#define B_  16
#define L_  96
#define D_  512
#define M_  (B_ * L_)
#define NPART 192
#define PSTRIDE (B_ * L_ * L_)

// ---------------- device scratch ------------------------------------------
__device__ float g_AB2[M_ * D_];       // [b][hp][i]
__device__ float g_C2[M_ * D_];        // [b][hp][j]
__device__ float g_P[4 * PSTRIDE];
__device__ float g_v4[4 * M_];
__device__ float g_partial[NPART];
__device__ int   g_perm[D_];
__device__ float g_w2a[D_];
__device__ int   g_Hpos;
__device__ __nv_bfloat16 g_Xh[M_ * D_];
__device__ __nv_bfloat16 g_Xl[M_ * D_];
__device__ __nv_bfloat16 g_Wth[1024 * D_];
__device__ __nv_bfloat16 g_Wtl[1024 * D_];

// ---------------- helpers ---------------------------------------------------
__device__ __forceinline__ uint32_t smem_u32(const void* p) {
    uint32_t a;
    asm("{ .reg .u64 t; cvta.to.shared.u64 t, %1; cvt.u32.u64 %0, t; }"
        : "=r"(a) : "l"(p));
    return a;
}
__device__ __forceinline__ void ldsm_x4(uint32_t* r, uint32_t addr) {
    asm volatile("ldmatrix.sync.aligned.m8n8.x4.shared.b16 {%0,%1,%2,%3}, [%4];"
                 : "=r"(r[0]), "=r"(r[1]), "=r"(r[2]), "=r"(r[3]) : "r"(addr));
}
__device__ __forceinline__ void mma_bf16(float* c, const uint32_t* a,
                                         uint32_t b0, uint32_t b1) {
    asm volatile(
        "mma.sync.aligned.m16n8k16.row.col.f32.bf16.bf16.f32 "
        "{%0,%1,%2,%3}, {%4,%5,%6,%7}, {%8,%9}, {%0,%1,%2,%3};"
        : "+f"(c[0]), "+f"(c[1]), "+f"(c[2]), "+f"(c[3])
        : "r"(a[0]), "r"(a[1]), "r"(a[2]), "r"(a[3]), "r"(b0), "r"(b1));
}
__device__ __forceinline__ void cp_async16(uint32_t saddr, const void* gaddr) {
    asm volatile("cp.async.cg.shared.global [%0], [%1], 16;"
                 :: "r"(saddr), "l"(gaddr));
}

// ---------------- kernel A: convert/split X, W1 + sign-partition perm ------
__global__ void __launch_bounds__(512)
convert_kernel(const float* __restrict__ X, const float* __restrict__ W1,
               const float* __restrict__ W2) {
    const int tid = threadIdx.x;
    const int bx = blockIdx.x;
    if (bx == 0) {
        __shared__ int wcnt[16], wpre[17];
        const int lane = tid & 31, w = tid >> 5;
        float v = W2[tid];
        bool pos = (v >= 0.f);
        unsigned mset = __ballot_sync(0xffffffffu, pos);
        int lpre = __popc(mset & ((1u << lane) - 1u));
        if (lane == 0) wcnt[w] = __popc(mset);
        __syncthreads();
        if (tid == 0) {
            int s = 0;
#pragma unroll
            for (int k = 0; k < 16; k++) { wpre[k] = s; s += wcnt[k]; }
            wpre[16] = s;
        }
        __syncthreads();
        int Hp = wpre[16];
        int posrank = wpre[w] + lpre;
        g_perm[tid] = pos ? posrank : (Hp + tid - posrank);
        g_w2a[tid] = fabsf(v);
        if (tid == 0) g_Hpos = Hp;
    } else if (bx < 385) {
        int idx = (bx - 1) * 512 + tid;
        float4 v = ((const float4*)X)[idx];
        __nv_bfloat16 hx = __float2bfloat16(v.x), hy = __float2bfloat16(v.y);
        __nv_bfloat16 hz = __float2bfloat16(v.z), hw = __float2bfloat16(v.w);
        __nv_bfloat16 lx = __float2bfloat16(v.x - __bfloat162float(hx));
        __nv_bfloat16 ly = __float2bfloat16(v.y - __bfloat162float(hy));
        __nv_bfloat16 lz = __float2bfloat16(v.z - __bfloat162float(hz));
        __nv_bfloat16 lw = __float2bfloat16(v.w - __bfloat162float(hw));
        ((__nv_bfloat162*)g_Xh)[idx * 2 + 0] = __nv_bfloat162(hx, hy);
        ((__nv_bfloat162*)g_Xh)[idx * 2 + 1] = __nv_bfloat162(hz, hw);
        ((__nv_bfloat162*)g_Xl)[idx * 2 + 0] = __nv_bfloat162(lx, ly);
        ((__nv_bfloat162*)g_Xl)[idx * 2 + 1] = __nv_bfloat162(lz, lw);
    } else {
        __shared__ float t[32][33];
        const int wb = bx - 385;
        const int p  = wb >> 8;
        const int k0 = ((wb >> 4) & 15) * 32;
        const int n0 = (wb & 15) * 32;
        const int tx = tid & 31, ty = tid >> 5;
#pragma unroll
        for (int r = 0; r < 32; r += 16)
            t[ty + r][tx] = W1[(size_t)(p * 512 + k0 + ty + r) * 512 + n0 + tx];
        __syncthreads();
#pragma unroll
        for (int r = 0; r < 32; r += 16) {
            float v = t[tx][ty + r];
            __nv_bfloat16 h = __float2bfloat16(v);
            __nv_bfloat16 l = __float2bfloat16(v - __bfloat162float(h));
            size_t o = (size_t)(p * 512 + n0 + ty + r) * 512 + k0 + tx;
            g_Wth[o] = h;
            g_Wtl[o] = l;
        }
    }
}

// ---------------- kernel B: bf16-split GEMM via mma.sync --------------------
#define BK 32
#define ASTRIDE 80
#define TILE_B (128 * ASTRIDE)
#define BUFB   (4 * TILE_B)
#define GEMM_SMEM (2 * BUFB)

__global__ void __launch_bounds__(256, 1)
gemm_mma_kernel(const float* __restrict__ b1) {
    extern __shared__ char smem[];
    const uint32_t smem_base = smem_u32(smem);
    const int tid = threadIdx.x, wid = tid >> 5, lane = tid & 31;
    const int n0 = blockIdx.x * 128;
    const int m0 = blockIdx.y * 128;
    const int m_off = (wid & 3) * 32;
    const int n_off = (wid >> 2) * 64;

    const __nv_bfloat16* srcs[4] = {
        g_Xh  + (size_t)m0 * 512, g_Xl  + (size_t)m0 * 512,
        g_Wth + (size_t)n0 * 512, g_Wtl + (size_t)n0 * 512};

    auto prefetch = [&](int c, int buf) {
        const uint32_t sm0 = smem_base + buf * BUFB;
#pragma unroll
        for (int it = 0; it < 8; it++) {
            int t = it * 256 + tid;
            int s = t >> 9, r = (t >> 2) & 127, q = t & 3;
            cp_async16(sm0 + s * TILE_B + r * ASTRIDE + q * 16,
                       srcs[s] + (size_t)r * 512 + c * BK + q * 8);
        }
    };

    float acc[2][8][4];
#pragma unroll
    for (int i = 0; i < 2; i++)
#pragma unroll
        for (int j = 0; j < 8; j++)
#pragma unroll
            for (int k = 0; k < 4; k++) acc[i][j][k] = 0.f;

    const int grp = lane >> 3, ln8 = lane & 7;
    const int a_row = (grp & 1) * 8 + ln8;
    const int a_kB  = (grp >> 1) * 16;
    const int b_row = ((grp >> 1) & 1) * 8 + ln8;
    const int b_kB  = (grp & 1) * 16;

    prefetch(0, 0);
    asm volatile("cp.async.commit_group;" ::: "memory");

    for (int c = 0; c < 16; c++) {
        const int buf = c & 1;
        if (c + 1 < 16) {
            prefetch(c + 1, buf ^ 1);
            asm volatile("cp.async.commit_group;" ::: "memory");
            asm volatile("cp.async.wait_group 1;" ::: "memory");
        } else {
            asm volatile("cp.async.wait_group 0;" ::: "memory");
        }
        __syncthreads();

        const uint32_t base = smem_base + buf * BUFB;
#pragma unroll
        for (int ks = 0; ks < 2; ks++) {
            const int kB = ks * 32;
            // hoisted fragment loads: each used by multiple passes
            uint32_t ah[2][4], al[2][4], bh[4][4], bl[4][4];
#pragma unroll
            for (int fm = 0; fm < 2; fm++) {
                const uint32_t ro = (m_off + fm * 16 + a_row) * ASTRIDE + kB + a_kB;
                ldsm_x4(ah[fm], base + ro);
                ldsm_x4(al[fm], base + TILE_B + ro);
            }
#pragma unroll
            for (int fp = 0; fp < 4; fp++) {
                const uint32_t ro = (n_off + fp * 16 + b_row) * ASTRIDE + kB + b_kB;
                ldsm_x4(bh[fp], base + 2 * TILE_B + ro);
                ldsm_x4(bl[fp], base + 3 * TILE_B + ro);
            }
#pragma unroll
            for (int fm = 0; fm < 2; fm++)
#pragma unroll
                for (int fp = 0; fp < 4; fp++) {
                    mma_bf16(acc[fm][2 * fp + 0], ah[fm], bh[fp][0], bh[fp][1]);
                    mma_bf16(acc[fm][2 * fp + 1], ah[fm], bh[fp][2], bh[fp][3]);
                    mma_bf16(acc[fm][2 * fp + 0], ah[fm], bl[fp][0], bl[fp][1]);
                    mma_bf16(acc[fm][2 * fp + 1], ah[fm], bl[fp][2], bl[fp][3]);
                    mma_bf16(acc[fm][2 * fp + 0], al[fm], bh[fp][0], bh[fp][1]);
                    mma_bf16(acc[fm][2 * fp + 1], al[fm], bh[fp][2], bh[fp][3]);
                }
        }
        __syncthreads();
    }

    // cache lookup tables in (now free) smem
    int*   sperm = (int*)smem;
    float* sw2a  = (float*)(smem + 2048);
    float* sb1   = (float*)(smem + 4096);
    const bool isA = (n0 < 512);
    for (int t = tid; t < 512; t += 256) {
        int h = isA ? (n0 + t) : (n0 - 512 + t);
        // only the 128 columns this block owns are needed; load those
        if (t < 128) {
            int col = (isA ? n0 : (n0 - 512)) + t;
            sperm[t] = g_perm[col];
            sw2a[t]  = g_w2a[col];
            if (isA) sb1[t] = b1[n0 + t];
        }
        (void)h;
    }
    __syncthreads();

    // epilogue: scatter into permuted/scaled h-major layout
    const int r0 = lane >> 2, cc = (lane & 3) * 2;
    float* dstBase = isA ? g_AB2 : g_C2;
#pragma unroll
    for (int fm = 0; fm < 2; fm++) {
        const int mr0 = m0 + m_off + fm * 16 + r0;
        const int mr1 = mr0 + 8;
        const int b0r = mr0 / 96, i0r = mr0 - b0r * 96;
        const int b1r = mr1 / 96, i1r = mr1 - b1r * 96;
#pragma unroll
        for (int fn = 0; fn < 8; fn++) {
            const int lc = n_off + fn * 8 + cc;   // 0..127 local column
            const float* a4 = acc[fm][fn];
#pragma unroll
            for (int e = 0; e < 2; e++) {
                const int l = lc + e;
                const int hp = sperm[l];
                const float sc = sw2a[l];
                const float add = isA ? sb1[l] : 0.f;
                dstBase[((size_t)(b0r * 512 + hp)) * 96 + i0r] = (a4[e]     + add) * sc;
                dstBase[((size_t)(b1r * 512 + hp)) * 96 + i1r] = (a4[2 + e] + add) * sc;
            }
        }
    }
}

// ---------------- kernel D: pairwise abs-sum + fused v ---------------------
// grid (4 h-slices, 2 i-tiles, 16 b); 256 thr = 16(i) x 16(j); 3x6 per thread
#define PW_SMEM ((128 * 48 + 128 * 96) * 4)

__global__ void __launch_bounds__(256)
pairwise_kernel() {
    extern __shared__ float ps[];
    float* As = ps;                 // [128][48]
    float* Cs = ps + 128 * 48;      // [128][96]

    const int hs = blockIdx.x;
    const int it = blockIdx.y;
    const int b  = blockIdx.z;
    const int tid = threadIdx.x;
    const int ty = tid >> 4, tx = tid & 15;
    const int il = 3 * ty, jl = 6 * tx;

    // fill smem
    const float4* srcA = (const float4*)(g_AB2 +
        ((size_t)(b * 512 + hs * 128)) * 96 + it * 48);
    const float4* srcC = (const float4*)(g_C2 +
        ((size_t)(b * 512 + hs * 128)) * 96);
    float4* dA = (float4*)As;
    float4* dC = (float4*)Cs;
#pragma unroll
    for (int t = tid; t < 1536; t += 256) {
        int r = t / 12, q = t - r * 12;
        dA[t] = srcA[r * 24 + q];
    }
#pragma unroll
    for (int t = tid; t < 3072; t += 256)
        dC[t] = srcC[t];
    __syncthreads();

    const int bnd = min(max(g_Hpos - hs * 128, 0), 128);
    float acc[3][6] = {{0.f}};
    float vac[6] = {0.f};

    int h = 0;
#pragma unroll 2
    for (; h < bnd; h++) {
        const float* Ar = &As[h * 48 + il];
        const float* Cr = &Cs[h * 96 + jl];
        float a0 = Ar[0], a1 = Ar[1], a2 = Ar[2];
        float2 c01 = *(const float2*)&Cr[0];
        float2 c23 = *(const float2*)&Cr[2];
        float2 c45 = *(const float2*)&Cr[4];
        float cv[6] = {c01.x, c01.y, c23.x, c23.y, c45.x, c45.y};
#pragma unroll
        for (int c = 0; c < 6; c++) {
            acc[0][c] += fabsf(a0 + cv[c]);
            acc[1][c] += fabsf(a1 + cv[c]);
            acc[2][c] += fabsf(a2 + cv[c]);
            vac[c] += cv[c];
        }
    }
#pragma unroll 2
    for (; h < 128; h++) {
        const float* Ar = &As[h * 48 + il];
        const float* Cr = &Cs[h * 96 + jl];
        float a0 = Ar[0], a1 = Ar[1], a2 = Ar[2];
        float2 c01 = *(const float2*)&Cr[0];
        float2 c23 = *(const float2*)&Cr[2];
        float2 c45 = *(const float2*)&Cr[4];
        float cv[6] = {c01.x, c01.y, c23.x, c23.y, c45.x, c45.y};
#pragma unroll
        for (int c = 0; c < 6; c++) {
            acc[0][c] -= fabsf(a0 + cv[c]);
            acc[1][c] -= fabsf(a1 + cv[c]);
            acc[2][c] -= fabsf(a2 + cv[c]);
            vac[c] -= cv[c];
        }
    }

    float* P = g_P + (size_t)hs * PSTRIDE +
               ((size_t)b * 96 + it * 48 + il) * 96 + jl;
#pragma unroll
    for (int r = 0; r < 3; r++) {
#pragma unroll
        for (int c = 0; c < 6; c += 2)
            *(float2*)&P[(size_t)r * 96 + c] = make_float2(acc[r][c], acc[r][c + 1]);
    }

    if (it == 0 && ty == 0) {
#pragma unroll
        for (int c = 0; c < 6; c += 2)
            *(float2*)&g_v4[hs * M_ + b * 96 + jl + c] = make_float2(vac[c], vac[c + 1]);
    }
}

// ---------------- kernel E: fused softmax-CE --------------------------------
__global__ void ce_kernel(const int* __restrict__ order) {
    __shared__ int   ord[96];
    __shared__ float vsh[96];
    __shared__ float rowbuf[8][96];
    __shared__ float wpart[8];

    const int b = blockIdx.y, tid = threadIdx.x;
    const int warp = tid >> 5, lane = tid & 31;
    const int i = blockIdx.x * 8 + warp;

    if (tid < 96) {
        ord[tid] = order[b * 96 + tid];
        vsh[tid] = g_v4[0 * M_ + b * 96 + tid] + g_v4[1 * M_ + b * 96 + tid]
                 + g_v4[2 * M_ + b * 96 + tid] + g_v4[3 * M_ + b * 96 + tid];
    }
    __syncthreads();

    const size_t ro = ((size_t)b * 96 + i) * 96;
    float lg[3];
#pragma unroll
    for (int r = 0; r < 3; r++) {
        int j = lane + r * 32;
        float P = g_P[ro + j] + g_P[PSTRIDE + ro + j]
                + g_P[2 * PSTRIDE + ro + j] + g_P[3 * PSTRIDE + ro + j];
        lg[r] = 0.55f * vsh[j] + 0.45f * P;
        rowbuf[warp][j] = lg[r];
    }

    float m = fmaxf(lg[0], fmaxf(lg[1], lg[2]));
#pragma unroll
    for (int o = 16; o > 0; o >>= 1)
        m = fmaxf(m, __shfl_xor_sync(0xffffffffu, m, o));
    float s = expf(lg[0] - m) + expf(lg[1] - m) + expf(lg[2] - m);
#pragma unroll
    for (int o = 16; o > 0; o >>= 1)
        s += __shfl_xor_sync(0xffffffffu, s, o);
    float lse = m + logf(s);

    int oi = ord[i];
    int o0 = ord[lane], o1 = ord[lane + 32], o2 = ord[lane + 64];
    unsigned t0 = __ballot_sync(0xffffffffu, o0 == oi + 1);
    unsigned t1 = __ballot_sync(0xffffffffu, o1 == oi + 1);
    unsigned t2 = __ballot_sync(0xffffffffu, o2 == oi + 1);
    int tgt = t0 ? (__ffs(t0) - 1)
                 : (t1 ? (31 + __ffs(t1)) : (t2 ? (63 + __ffs(t2)) : 0));

    int mx = max(o0, max(o1, o2));
#pragma unroll
    for (int o = 16; o > 0; o >>= 1)
        mx = max(mx, __shfl_xor_sync(0xffffffffu, mx, o));
    unsigned M0 = __ballot_sync(0xffffffffu, o0 == mx);
    unsigned M1 = __ballot_sync(0xffffffffu, o1 == mx);
    unsigned M2 = __ballot_sync(0xffffffffu, o2 == mx);
    int last = M0 ? (__ffs(M0) - 1) : (M1 ? (31 + __ffs(M1)) : (63 + __ffs(M2)));

    float contrib = (i == last) ? 0.f : (lse - rowbuf[warp][tgt]);
    if (lane == 0) wpart[warp] = contrib;
    __syncthreads();
    if (tid == 0) {
        float ssum = 0.f;
#pragma unroll
        for (int w = 0; w < 8; w++) ssum += wpart[w];
        g_partial[b * 12 + blockIdx.x] = ssum;
    }
}

// ---------------- kernel F: parallel final reduction ------------------------
__global__ void finalize_kernel(float* __restrict__ out) {
    __shared__ float wsum[8];
    const int t = threadIdx.x, lane = t & 31, w = t >> 5;
    float v = (t < NPART) ? g_partial[t] : 0.f;
#pragma unroll
    for (int o = 16; o > 0; o >>= 1)
        v += __shfl_xor_sync(0xffffffffu, v, o);
    if (lane == 0) wsum[w] = v;
    __syncthreads();
    if (t == 0) {
        float s = 0.f;
#pragma unroll
        for (int k = 0; k < 8; k++) s += wsum[k];
        out[0] = s * (1.0f / (16.0f * 95.0f));
    }
}

// ---------------- launcher --------------------------------------------------
extern "C" void kernel_launch(void* const* d_in, const int* in_sizes, int n_in,
                              void* d_out, int out_size) {
    const float* X    = (const float*)d_in[0];
    const float* W1   = (const float*)d_in[1];
    const float* b1   = (const float*)d_in[2];
    const float* W2   = (const float*)d_in[3];
    const int*   order = (const int*)d_in[6];

    static bool attr_set = false;
    if (!attr_set) {
        cudaFuncSetAttribute(gemm_mma_kernel,
                             cudaFuncAttributeMaxDynamicSharedMemorySize, GEMM_SMEM);
        cudaFuncSetAttribute(pairwise_kernel,
                             cudaFuncAttributeMaxDynamicSharedMemorySize, PW_SMEM);
        attr_set = true;
    }

    convert_kernel<<<897, 512>>>(X, W1, W2);
    gemm_mma_kernel<<<dim3(8, 12), 256, GEMM_SMEM>>>(b1);
    pairwise_kernel<<<dim3(4, 2, 16), 256, PW_SMEM>>>();
    ce_kernel<<<dim3(12, 16), 256>>>(order);
    finalize_kernel<<<1, 256>>>((float*)d_out);
}

// round 10
// speedup vs baseline: 2.8474x; 1.2272x over previous
#include <cuda_runtime.h>
#include <cuda_fp16.h>
#include <cstdint>

#define B_  16
#define L_  96
#define D_  512
#define M_  (B_ * L_)
#define NPART 192
#define PSTRIDE (B_ * L_ * L_)

// ---------------- device scratch ------------------------------------------
__device__ float g_AB2[M_ * D_];       // [b][hp][i]: (a+b1)*|w2|, permuted h
__device__ float g_C2[M_ * D_];        // [b][hp][j]: c*|w2|, permuted h
__device__ float g_P[4 * PSTRIDE];
__device__ float g_v4[4 * M_];
__device__ float g_partial[NPART];
__device__ int   g_perm[D_];
__device__ float g_w2a[D_];
__device__ float g_b1s[D_];            // b1[h]*|w2[h]| at permuted index
__device__ int   g_Hpos;
__device__ int   g_ctr;                // arrival counter (self-resetting)
__device__ __half g_Xf[M_ * D_];
__device__ __half g_Wt[1024 * D_];     // [n][k], |w2|-scaled, perm rows

// ---------------- helpers ---------------------------------------------------
__device__ __forceinline__ uint32_t smem_u32(const void* p) {
    uint32_t a;
    asm("{ .reg .u64 t; cvta.to.shared.u64 t, %1; cvt.u32.u64 %0, t; }"
        : "=r"(a) : "l"(p));
    return a;
}
__device__ __forceinline__ void ldsm_x4(uint32_t* r, uint32_t addr) {
    asm volatile("ldmatrix.sync.aligned.m8n8.x4.shared.b16 {%0,%1,%2,%3}, [%4];"
                 : "=r"(r[0]), "=r"(r[1]), "=r"(r[2]), "=r"(r[3]) : "r"(addr));
}
__device__ __forceinline__ void mma_f16(float* c, const uint32_t* a,
                                        uint32_t b0, uint32_t b1) {
    asm volatile(
        "mma.sync.aligned.m16n8k16.row.col.f32.f16.f16.f32 "
        "{%0,%1,%2,%3}, {%4,%5,%6,%7}, {%8,%9}, {%0,%1,%2,%3};"
        : "+f"(c[0]), "+f"(c[1]), "+f"(c[2]), "+f"(c[3])
        : "r"(a[0]), "r"(a[1]), "r"(a[2]), "r"(a[3]), "r"(b0), "r"(b1));
}
__device__ __forceinline__ void cp_async16(uint32_t saddr, const void* gaddr) {
    asm volatile("cp.async.cg.shared.global [%0], [%1], 16;"
                 :: "r"(saddr), "l"(gaddr));
}

// ---------------- kernel 0: sign-partition perm + scaled b1 ----------------
__global__ void __launch_bounds__(512)
perm_kernel(const float* __restrict__ W2, const float* __restrict__ b1) {
    __shared__ int wcnt[16], wpre[17];
    const int tid = threadIdx.x;
    const int lane = tid & 31, w = tid >> 5;
    float v = W2[tid];
    bool pos = (v >= 0.f);
    unsigned mset = __ballot_sync(0xffffffffu, pos);
    int lpre = __popc(mset & ((1u << lane) - 1u));
    if (lane == 0) wcnt[w] = __popc(mset);
    __syncthreads();
    if (tid == 0) {
        int s = 0;
#pragma unroll
        for (int k = 0; k < 16; k++) { wpre[k] = s; s += wcnt[k]; }
        wpre[16] = s;
    }
    __syncthreads();
    int Hp = wpre[16];
    int posrank = wpre[w] + lpre;
    int myperm = pos ? posrank : (Hp + tid - posrank);
    g_perm[tid] = myperm;
    g_w2a[tid] = fabsf(v);
    g_b1s[myperm] = b1[tid] * fabsf(v);
    if (tid == 0) g_Hpos = Hp;
}

// ---------------- kernel A: convert X -> fp16, W1 -> scaled/perm fp16 T ----
__global__ void __launch_bounds__(512)
convert_kernel(const float* __restrict__ X, const float* __restrict__ W1) {
    const int tid = threadIdx.x;
    const int bx = blockIdx.x;
    if (bx < 384) {
        int idx = bx * 512 + tid;                 // over 196608 float4
        float4 v = ((const float4*)X)[idx];
        ((__half2*)g_Xf)[idx * 2 + 0] = __floats2half2_rn(v.x, v.y);
        ((__half2*)g_Xf)[idx * 2 + 1] = __floats2half2_rn(v.z, v.w);
    } else {
        __shared__ float t[32][33];
        __shared__ int   perm_sh[32];
        __shared__ float w2a_sh[32];
        const int wb = bx - 384;                  // 0..511
        const int p  = wb >> 8;
        const int k0 = ((wb >> 4) & 15) * 32;
        const int n0 = (wb & 15) * 32;
        const int tx = tid & 31, ty = tid >> 5;   // (32,16)
        if (tid < 32) {
            perm_sh[tid] = g_perm[n0 + tid];
            w2a_sh[tid]  = g_w2a[n0 + tid];
        }
#pragma unroll
        for (int r = 0; r < 32; r += 16)
            t[ty + r][tx] = W1[(size_t)(p * 512 + k0 + ty + r) * 512 + n0 + tx];
        __syncthreads();
#pragma unroll
        for (int r = 0; r < 32; r += 16) {
            float v = t[tx][ty + r] * w2a_sh[ty + r];
            size_t o = (size_t)(p * 512 + perm_sh[ty + r]) * 512 + k0 + tx;
            g_Wt[o] = __float2half_rn(v);
        }
    }
}

// ---------------- kernel B: single-pass fp16 GEMM via mma.sync --------------
#define GASTRIDE 80
#define G_ATILE (128 * GASTRIDE)        // 10240
#define G_STAGE (2 * G_ATILE)           // 20480
#define GEMM_SMEM (3 * G_STAGE)         // 61440

__global__ void __launch_bounds__(256, 1)
gemm_mma_kernel() {
    extern __shared__ char smem[];
    const uint32_t smem_base = smem_u32(smem);
    const int tid = threadIdx.x, wid = tid >> 5, lane = tid & 31;
    const int n0 = blockIdx.x * 128;
    const int m0 = blockIdx.y * 128;
    const int m_off = (wid & 3) * 32;
    const int n_off = (wid >> 2) * 64;

    const __half* srcA = g_Xf + (size_t)m0 * 512;
    const __half* srcB = g_Wt + (size_t)n0 * 512;

    // per-thread prefetch coords: one row each (256 rows/stage)
    const bool isArow = (tid < 128);
    const __half* prow = isArow ? (srcA + (size_t)tid * 512)
                                : (srcB + (size_t)(tid - 128) * 512);
    const uint32_t pdst = (isArow ? tid * GASTRIDE
                                  : G_ATILE + (tid - 128) * GASTRIDE);

    auto prefetch = [&](int c, int buf) {
        const uint32_t d = smem_base + buf * G_STAGE + pdst;
        const __half* s = prow + c * 32;
#pragma unroll
        for (int q = 0; q < 4; q++)
            cp_async16(d + q * 16, s + q * 8);
    };

    float acc[2][8][4];
#pragma unroll
    for (int i = 0; i < 2; i++)
#pragma unroll
        for (int j = 0; j < 8; j++)
#pragma unroll
            for (int k = 0; k < 4; k++) acc[i][j][k] = 0.f;

    const int grp = lane >> 3, ln8 = lane & 7;
    const int a_row = (grp & 1) * 8 + ln8;
    const int a_kB  = (grp >> 1) * 16;
    const int b_row = ((grp >> 1) & 1) * 8 + ln8;
    const int b_kB  = (grp & 1) * 16;

    prefetch(0, 0);
    asm volatile("cp.async.commit_group;" ::: "memory");
    prefetch(1, 1);
    asm volatile("cp.async.commit_group;" ::: "memory");

    for (int c = 0; c < 16; c++) {
        if (c + 2 < 16) {
            asm volatile("cp.async.wait_group 1;" ::: "memory");
        } else {
            asm volatile("cp.async.wait_group 0;" ::: "memory");
        }
        __syncthreads();
        if (c + 2 < 16) {
            prefetch(c + 2, (c + 2) % 3);
            asm volatile("cp.async.commit_group;" ::: "memory");
        }

        const uint32_t base = smem_base + (c % 3) * G_STAGE;
        const uint32_t Bb = base + G_ATILE;
#pragma unroll
        for (int ks = 0; ks < 2; ks++) {
            const int kB = ks * 32;
            uint32_t a[2][4], b[4][4];
#pragma unroll
            for (int fm = 0; fm < 2; fm++)
                ldsm_x4(a[fm], base + (m_off + fm * 16 + a_row) * GASTRIDE
                                    + kB + a_kB);
#pragma unroll
            for (int fp = 0; fp < 4; fp++)
                ldsm_x4(b[fp], Bb + (n_off + fp * 16 + b_row) * GASTRIDE
                                  + kB + b_kB);
#pragma unroll
            for (int fm = 0; fm < 2; fm++)
#pragma unroll
                for (int fp = 0; fp < 4; fp++) {
                    mma_f16(acc[fm][2 * fp + 0], a[fm], b[fp][0], b[fp][1]);
                    mma_f16(acc[fm][2 * fp + 1], a[fm], b[fp][2], b[fp][3]);
                }
        }
        __syncthreads();
    }

    // b1s table for A-half blocks
    float* sb1 = (float*)smem;
    const bool isA = (n0 < 512);
    if (isA && tid < 128) sb1[tid] = g_b1s[n0 + tid];
    __syncthreads();

    // epilogue: straight write, rows already permuted/scaled via Wt
    const int r0 = lane >> 2, cc = (lane & 3) * 2;
    float* dstBase = isA ? g_AB2 : g_C2;
    const int nbase = isA ? n0 : (n0 - 512);
#pragma unroll
    for (int fm = 0; fm < 2; fm++) {
        const int mr0 = m0 + m_off + fm * 16 + r0;
        const int mr1 = mr0 + 8;
        const int b0r = mr0 / 96, i0r = mr0 - b0r * 96;
        const int b1r = mr1 / 96, i1r = mr1 - b1r * 96;
#pragma unroll
        for (int fn = 0; fn < 8; fn++) {
            const int lc = n_off + fn * 8 + cc;
            const float* a4 = acc[fm][fn];
#pragma unroll
            for (int e = 0; e < 2; e++) {
                const int l = lc + e;
                const float add = isA ? sb1[l] : 0.f;
                dstBase[((size_t)(b0r * 512 + nbase + l)) * 96 + i0r] = a4[e] + add;
                dstBase[((size_t)(b1r * 512 + nbase + l)) * 96 + i1r] = a4[2 + e] + add;
            }
        }
    }
}

// ---------------- kernel D: pairwise abs-sum + fused v ---------------------
#define PW_SMEM ((128 * 48 + 128 * 96) * 4)

__global__ void __launch_bounds__(256)
pairwise_kernel() {
    extern __shared__ float ps[];
    float* As = ps;                 // [128][48]
    float* Cs = ps + 128 * 48;      // [128][96]

    const int hs = blockIdx.x;
    const int it = blockIdx.y;
    const int b  = blockIdx.z;
    const int tid = threadIdx.x;
    const int ty = tid >> 4, tx = tid & 15;
    const int il = 3 * ty, jl = 6 * tx;

    const float4* srcA = (const float4*)(g_AB2 +
        ((size_t)(b * 512 + hs * 128)) * 96 + it * 48);
    const float4* srcC = (const float4*)(g_C2 +
        ((size_t)(b * 512 + hs * 128)) * 96);
    float4* dA = (float4*)As;
    float4* dC = (float4*)Cs;
#pragma unroll
    for (int t = tid; t < 1536; t += 256) {
        int r = t / 12, q = t - r * 12;
        dA[t] = srcA[r * 24 + q];
    }
#pragma unroll
    for (int t = tid; t < 3072; t += 256)
        dC[t] = srcC[t];
    __syncthreads();

    const int bnd = min(max(g_Hpos - hs * 128, 0), 128);
    float acc[3][6] = {{0.f}};
    float vac[6] = {0.f};

    int h = 0;
#pragma unroll 2
    for (; h < bnd; h++) {
        const float* Ar = &As[h * 48 + il];
        const float* Cr = &Cs[h * 96 + jl];
        float a0 = Ar[0], a1 = Ar[1], a2 = Ar[2];
        float2 c01 = *(const float2*)&Cr[0];
        float2 c23 = *(const float2*)&Cr[2];
        float2 c45 = *(const float2*)&Cr[4];
        float cv[6] = {c01.x, c01.y, c23.x, c23.y, c45.x, c45.y};
#pragma unroll
        for (int c = 0; c < 6; c++) {
            acc[0][c] += fabsf(a0 + cv[c]);
            acc[1][c] += fabsf(a1 + cv[c]);
            acc[2][c] += fabsf(a2 + cv[c]);
            vac[c] += cv[c];
        }
    }
#pragma unroll 2
    for (; h < 128; h++) {
        const float* Ar = &As[h * 48 + il];
        const float* Cr = &Cs[h * 96 + jl];
        float a0 = Ar[0], a1 = Ar[1], a2 = Ar[2];
        float2 c01 = *(const float2*)&Cr[0];
        float2 c23 = *(const float2*)&Cr[2];
        float2 c45 = *(const float2*)&Cr[4];
        float cv[6] = {c01.x, c01.y, c23.x, c23.y, c45.x, c45.y};
#pragma unroll
        for (int c = 0; c < 6; c++) {
            acc[0][c] -= fabsf(a0 + cv[c]);
            acc[1][c] -= fabsf(a1 + cv[c]);
            acc[2][c] -= fabsf(a2 + cv[c]);
            vac[c] -= cv[c];
        }
    }

    float* P = g_P + (size_t)hs * PSTRIDE +
               ((size_t)b * 96 + it * 48 + il) * 96 + jl;
#pragma unroll
    for (int r = 0; r < 3; r++) {
#pragma unroll
        for (int c = 0; c < 6; c += 2)
            *(float2*)&P[(size_t)r * 96 + c] = make_float2(acc[r][c], acc[r][c + 1]);
    }

    if (it == 0 && ty == 0) {
#pragma unroll
        for (int c = 0; c < 6; c += 2)
            *(float2*)&g_v4[hs * M_ + b * 96 + jl + c] = make_float2(vac[c], vac[c + 1]);
    }
}

// ---------------- kernel E: fused softmax-CE + final reduce -----------------
__global__ void ce_kernel(const int* __restrict__ order, float* __restrict__ out) {
    __shared__ int   ord[96];
    __shared__ float vsh[96];
    __shared__ float rowbuf[8][96];
    __shared__ float wpart[8];
    __shared__ int   slast;

    const int b = blockIdx.y, tid = threadIdx.x;
    const int warp = tid >> 5, lane = tid & 31;
    const int i = blockIdx.x * 8 + warp;

    if (tid < 96) {
        ord[tid] = order[b * 96 + tid];
        vsh[tid] = g_v4[0 * M_ + b * 96 + tid] + g_v4[1 * M_ + b * 96 + tid]
                 + g_v4[2 * M_ + b * 96 + tid] + g_v4[3 * M_ + b * 96 + tid];
    }
    __syncthreads();

    const size_t ro = ((size_t)b * 96 + i) * 96;
    float lg[3];
#pragma unroll
    for (int r = 0; r < 3; r++) {
        int j = lane + r * 32;
        float P = g_P[ro + j] + g_P[PSTRIDE + ro + j]
                + g_P[2 * PSTRIDE + ro + j] + g_P[3 * PSTRIDE + ro + j];
        lg[r] = 0.55f * vsh[j] + 0.45f * P;
        rowbuf[warp][j] = lg[r];
    }

    float m = fmaxf(lg[0], fmaxf(lg[1], lg[2]));
#pragma unroll
    for (int o = 16; o > 0; o >>= 1)
        m = fmaxf(m, __shfl_xor_sync(0xffffffffu, m, o));
    float s = expf(lg[0] - m) + expf(lg[1] - m) + expf(lg[2] - m);
#pragma unroll
    for (int o = 16; o > 0; o >>= 1)
        s += __shfl_xor_sync(0xffffffffu, s, o);
    float lse = m + logf(s);

    int oi = ord[i];
    int o0 = ord[lane], o1 = ord[lane + 32], o2 = ord[lane + 64];
    unsigned t0 = __ballot_sync(0xffffffffu, o0 == oi + 1);
    unsigned t1 = __ballot_sync(0xffffffffu, o1 == oi + 1);
    unsigned t2 = __ballot_sync(0xffffffffu, o2 == oi + 1);
    int tgt = t0 ? (__ffs(t0) - 1)
                 : (t1 ? (31 + __ffs(t1)) : (t2 ? (63 + __ffs(t2)) : 0));

    int mx = max(o0, max(o1, o2));
#pragma unroll
    for (int o = 16; o > 0; o >>= 1)
        mx = max(mx, __shfl_xor_sync(0xffffffffu, mx, o));
    unsigned M0 = __ballot_sync(0xffffffffu, o0 == mx);
    unsigned M1 = __ballot_sync(0xffffffffu, o1 == mx);
    unsigned M2 = __ballot_sync(0xffffffffu, o2 == mx);
    int last = M0 ? (__ffs(M0) - 1) : (M1 ? (31 + __ffs(M1)) : (63 + __ffs(M2)));

    float contrib = (i == last) ? 0.f : (lse - rowbuf[warp][tgt]);
    if (lane == 0) wpart[warp] = contrib;
    __syncthreads();
    if (tid == 0) {
        float ssum = 0.f;
#pragma unroll
        for (int w = 0; w < 8; w++) ssum += wpart[w];
        g_partial[b * 12 + blockIdx.x] = ssum;
        __threadfence();
        slast = (atomicAdd(&g_ctr, 1) == NPART - 1) ? 1 : 0;
    }
    __syncthreads();

    // last-arriving block performs the deterministic final reduction
    if (slast) {
        __threadfence();
        __shared__ float wsum[8];
        float v = (tid < NPART) ? g_partial[tid] : 0.f;
#pragma unroll
        for (int o = 16; o > 0; o >>= 1)
            v += __shfl_xor_sync(0xffffffffu, v, o);
        if (lane == 0) wsum[warp] = v;
        __syncthreads();
        if (tid == 0) {
            float ss = 0.f;
#pragma unroll
            for (int k = 0; k < 8; k++) ss += wsum[k];
            out[0] = ss * (1.0f / (16.0f * 95.0f));
            g_ctr = 0;   // reset for next graph replay
        }
    }
}

// ---------------- launcher --------------------------------------------------
extern "C" void kernel_launch(void* const* d_in, const int* in_sizes, int n_in,
                              void* d_out, int out_size) {
    const float* X    = (const float*)d_in[0];
    const float* W1   = (const float*)d_in[1];
    const float* b1   = (const float*)d_in[2];
    const float* W2   = (const float*)d_in[3];
    const int*   order = (const int*)d_in[6];

    static bool attr_set = false;
    if (!attr_set) {
        cudaFuncSetAttribute(gemm_mma_kernel,
                             cudaFuncAttributeMaxDynamicSharedMemorySize, GEMM_SMEM);
        cudaFuncSetAttribute(pairwise_kernel,
                             cudaFuncAttributeMaxDynamicSharedMemorySize, PW_SMEM);
        attr_set = true;
    }

    perm_kernel<<<1, 512>>>(W2, b1);
    convert_kernel<<<896, 512>>>(X, W1);
    gemm_mma_kernel<<<dim3(8, 12), 256, GEMM_SMEM>>>();
    pairwise_kernel<<<dim3(4, 2, 16), 256, PW_SMEM>>>();
    ce_kernel<<<dim3(12, 16), 256>>>(order, (float*)d_out);
}

// round 11
// speedup vs baseline: 3.1440x; 1.1042x over previous
#include <cuda_runtime.h>
#include <cuda_fp16.h>
#include <cstdint>

#define B_  16
#define L_  96
#define D_  512
#define M_  (B_ * L_)
#define NPART 192
#define PSTRIDE (B_ * L_ * L_)
#define NSLICE 8                        // pairwise h-slices (64 each)

// ---------------- device scratch ------------------------------------------
__device__ float g_AB2[M_ * D_];       // [b][hp][i]: (a+b1)*|w2|, permuted h
__device__ float g_C2[M_ * D_];        // [b][hp][j]: c*|w2|, permuted h
__device__ float g_P[NSLICE * PSTRIDE];
__device__ float g_v4[4 * M_];         // v partials per GEMM n-block
__device__ float g_partial[NPART];
__device__ float g_b1s[D_];            // b1[h]*|w2[h]| at permuted index
__device__ int   g_Hpos;
__device__ int   g_ctr;                // arrival counter (self-resetting)
__device__ __half g_Xf[M_ * D_];
__device__ __half g_Wt[1024 * D_];     // [n][k], |w2|-scaled, perm rows

// ---------------- helpers ---------------------------------------------------
__device__ __forceinline__ uint32_t smem_u32(const void* p) {
    uint32_t a;
    asm("{ .reg .u64 t; cvta.to.shared.u64 t, %1; cvt.u32.u64 %0, t; }"
        : "=r"(a) : "l"(p));
    return a;
}
__device__ __forceinline__ void ldsm_x4(uint32_t* r, uint32_t addr) {
    asm volatile("ldmatrix.sync.aligned.m8n8.x4.shared.b16 {%0,%1,%2,%3}, [%4];"
                 : "=r"(r[0]), "=r"(r[1]), "=r"(r[2]), "=r"(r[3]) : "r"(addr));
}
__device__ __forceinline__ void mma_f16(float* c, const uint32_t* a,
                                        uint32_t b0, uint32_t b1) {
    asm volatile(
        "mma.sync.aligned.m16n8k16.row.col.f32.f16.f16.f32 "
        "{%0,%1,%2,%3}, {%4,%5,%6,%7}, {%8,%9}, {%0,%1,%2,%3};"
        : "+f"(c[0]), "+f"(c[1]), "+f"(c[2]), "+f"(c[3])
        : "r"(a[0]), "r"(a[1]), "r"(a[2]), "r"(a[3]), "r"(b0), "r"(b1));
}
__device__ __forceinline__ void cp_async16(uint32_t saddr, const void* gaddr) {
    asm volatile("cp.async.cg.shared.global [%0], [%1], 16;"
                 :: "r"(saddr), "l"(gaddr));
}

// ---------------- kernel A: convert (X -> fp16) + (W1 -> scaled/perm T) ----
// blocks [0,384): X split. blocks [384,896): W1, with inlined sign-partition.
__global__ void __launch_bounds__(512)
convert_kernel(const float* __restrict__ X, const float* __restrict__ W1,
               const float* __restrict__ W2, const float* __restrict__ b1) {
    const int tid = threadIdx.x;
    const int bx = blockIdx.x;
    if (bx < 384) {
        int idx = bx * 512 + tid;                 // over 196608 float4
        float4 v = ((const float4*)X)[idx];
        ((__half2*)g_Xf)[idx * 2 + 0] = __floats2half2_rn(v.x, v.y);
        ((__half2*)g_Xf)[idx * 2 + 1] = __floats2half2_rn(v.z, v.w);
    } else {
        __shared__ float t[32][33];
        __shared__ int   sperm[512];
        __shared__ float sw2a[512];
        __shared__ int   wcnt[16], wpre[17];

        // inlined deterministic sign-partition of h by sign(w2)
        const int lane = tid & 31, w = tid >> 5;
        float v2 = W2[tid];
        bool pos = (v2 >= 0.f);
        unsigned mset = __ballot_sync(0xffffffffu, pos);
        int lpre = __popc(mset & ((1u << lane) - 1u));
        if (lane == 0) wcnt[w] = __popc(mset);
        __syncthreads();
        if (tid == 0) {
            int s = 0;
#pragma unroll
            for (int k = 0; k < 16; k++) { wpre[k] = s; s += wcnt[k]; }
            wpre[16] = s;
        }
        __syncthreads();
        const int Hp = wpre[16];
        int posrank = wpre[w] + lpre;
        sperm[tid] = pos ? posrank : (Hp + tid - posrank);
        sw2a[tid] = fabsf(v2);
        __syncthreads();

        const int wb = bx - 384;                  // 0..511
        const int p  = wb >> 8;
        const int k0 = ((wb >> 4) & 15) * 32;
        const int n0 = (wb & 15) * 32;
        const int tx = tid & 31, ty = tid >> 5;   // (32,16)

        if (wb == 0 && tid == 0) g_Hpos = Hp;
        if (p == 0 && k0 == 0 && tid < 32) {
            int h = n0 + tid;
            g_b1s[sperm[h]] = b1[h] * sw2a[h];
        }
#pragma unroll
        for (int r = 0; r < 32; r += 16)
            t[ty + r][tx] = W1[(size_t)(p * 512 + k0 + ty + r) * 512 + n0 + tx];
        __syncthreads();
#pragma unroll
        for (int r = 0; r < 32; r += 16) {
            const int h = n0 + ty + r;
            float v = t[tx][ty + r] * sw2a[h];
            size_t o = (size_t)(p * 512 + sperm[h]) * 512 + k0 + tx;
            g_Wt[o] = __float2half_rn(v);
        }
    }
}

// ---------------- kernel B: single-pass fp16 GEMM via mma.sync --------------
#define GASTRIDE 80
#define G_ATILE (128 * GASTRIDE)        // 10240
#define G_STAGE (2 * G_ATILE)           // 20480
#define GEMM_SMEM (3 * G_STAGE)         // 61440

__global__ void __launch_bounds__(256, 1)
gemm_mma_kernel() {
    extern __shared__ char smem[];
    const uint32_t smem_base = smem_u32(smem);
    const int tid = threadIdx.x, wid = tid >> 5, lane = tid & 31;
    const int n0 = blockIdx.x * 128;
    const int m0 = blockIdx.y * 128;
    const int m_off = (wid & 3) * 32;
    const int n_off = (wid >> 2) * 64;

    const __half* srcA = g_Xf + (size_t)m0 * 512;
    const __half* srcB = g_Wt + (size_t)n0 * 512;

    const bool isArow = (tid < 128);
    const __half* prow = isArow ? (srcA + (size_t)tid * 512)
                                : (srcB + (size_t)(tid - 128) * 512);
    const uint32_t pdst = (isArow ? tid * GASTRIDE
                                  : G_ATILE + (tid - 128) * GASTRIDE);

    auto prefetch = [&](int c, int buf) {
        const uint32_t d = smem_base + buf * G_STAGE + pdst;
        const __half* s = prow + c * 32;
#pragma unroll
        for (int q = 0; q < 4; q++)
            cp_async16(d + q * 16, s + q * 8);
    };

    float acc[2][8][4];
#pragma unroll
    for (int i = 0; i < 2; i++)
#pragma unroll
        for (int j = 0; j < 8; j++)
#pragma unroll
            for (int k = 0; k < 4; k++) acc[i][j][k] = 0.f;

    const int grp = lane >> 3, ln8 = lane & 7;
    const int a_row = (grp & 1) * 8 + ln8;
    const int a_kB  = (grp >> 1) * 16;
    const int b_row = ((grp >> 1) & 1) * 8 + ln8;
    const int b_kB  = (grp & 1) * 16;

    prefetch(0, 0);
    asm volatile("cp.async.commit_group;" ::: "memory");
    prefetch(1, 1);
    asm volatile("cp.async.commit_group;" ::: "memory");

    for (int c = 0; c < 16; c++) {
        if (c + 2 < 16) {
            asm volatile("cp.async.wait_group 1;" ::: "memory");
        } else {
            asm volatile("cp.async.wait_group 0;" ::: "memory");
        }
        __syncthreads();
        if (c + 2 < 16) {
            prefetch(c + 2, (c + 2) % 3);
            asm volatile("cp.async.commit_group;" ::: "memory");
        }

        const uint32_t base = smem_base + (c % 3) * G_STAGE;
        const uint32_t Bb = base + G_ATILE;
#pragma unroll
        for (int ks = 0; ks < 2; ks++) {
            const int kB = ks * 32;
            uint32_t a[2][4], b[4][4];
#pragma unroll
            for (int fm = 0; fm < 2; fm++)
                ldsm_x4(a[fm], base + (m_off + fm * 16 + a_row) * GASTRIDE
                                    + kB + a_kB);
#pragma unroll
            for (int fp = 0; fp < 4; fp++)
                ldsm_x4(b[fp], Bb + (n_off + fp * 16 + b_row) * GASTRIDE
                                  + kB + b_kB);
#pragma unroll
            for (int fm = 0; fm < 2; fm++)
#pragma unroll
                for (int fp = 0; fp < 4; fp++) {
                    mma_f16(acc[fm][2 * fp + 0], a[fm], b[fp][0], b[fp][1]);
                    mma_f16(acc[fm][2 * fp + 1], a[fm], b[fp][2], b[fp][3]);
                }
        }
        __syncthreads();
    }

    const bool isA = (n0 < 512);
    const int nbase = isA ? n0 : (n0 - 512);
    const int r0 = lane >> 2, cc = (lane & 3) * 2;

    // ---- C-half blocks: signed column sums -> g_v4 (deterministic) ----
    if (!isA) {
        const int Hpos = g_Hpos;
        float s[4] = {0.f, 0.f, 0.f, 0.f};
#pragma unroll
        for (int fm = 0; fm < 2; fm++)
#pragma unroll
            for (int fn = 0; fn < 8; fn++)
#pragma unroll
                for (int e = 0; e < 2; e++) {
                    const int l = n_off + fn * 8 + cc + e;
                    const float sg = (nbase + l < Hpos) ? 1.f : -1.f;
                    s[fm * 2 + 0] += sg * acc[fm][fn][e];
                    s[fm * 2 + 1] += sg * acc[fm][fn][2 + e];
                }
#pragma unroll
        for (int q = 0; q < 4; q++) {
            s[q] += __shfl_xor_sync(0xffffffffu, s[q], 1);
            s[q] += __shfl_xor_sync(0xffffffffu, s[q], 2);
        }
        float* svv = (float*)smem;
        if (wid < 4 && (lane & 3) == 0) {
            svv[m_off +  0 + r0] = s[0];
            svv[m_off +  8 + r0] = s[1];
            svv[m_off + 16 + r0] = s[2];
            svv[m_off + 24 + r0] = s[3];
        }
        __syncthreads();
        if (wid >= 4 && (lane & 3) == 0) {
            svv[m_off +  0 + r0] += s[0];
            svv[m_off +  8 + r0] += s[1];
            svv[m_off + 16 + r0] += s[2];
            svv[m_off + 24 + r0] += s[3];
        }
        __syncthreads();
        if (tid < 128)
            g_v4[(blockIdx.x - 4) * M_ + m0 + tid] = svv[tid];
    }

    // b1s table for A-half blocks
    float* sb1 = (float*)smem;
    if (isA) {
        if (tid < 128) sb1[tid] = g_b1s[n0 + tid];
        __syncthreads();
    }

    // epilogue: straight write, rows already permuted/scaled via Wt
    float* dstBase = isA ? g_AB2 : g_C2;
#pragma unroll
    for (int fm = 0; fm < 2; fm++) {
        const int mr0 = m0 + m_off + fm * 16 + r0;
        const int mr1 = mr0 + 8;
        const int b0r = mr0 / 96, i0r = mr0 - b0r * 96;
        const int b1r = mr1 / 96, i1r = mr1 - b1r * 96;
#pragma unroll
        for (int fn = 0; fn < 8; fn++) {
            const int lc = n_off + fn * 8 + cc;
            const float* a4 = acc[fm][fn];
#pragma unroll
            for (int e = 0; e < 2; e++) {
                const int l = lc + e;
                const float add = isA ? sb1[l] : 0.f;
                dstBase[((size_t)(b0r * 512 + nbase + l)) * 96 + i0r] = a4[e] + add;
                dstBase[((size_t)(b1r * 512 + nbase + l)) * 96 + i1r] = a4[2 + e] + add;
            }
        }
    }
}

// ---------------- kernel D: pairwise abs-sum (64-h slices) -----------------
// grid (8 h-slices, 2 i-tiles, 16 b); 256 thr = 16(i) x 16(j); 3x6 per thread
__global__ void __launch_bounds__(256)
pairwise_kernel() {
    __shared__ __align__(16) float As[64 * 48];
    __shared__ __align__(16) float Cs[64 * 96];

    const int hs = blockIdx.x;
    const int it = blockIdx.y;
    const int b  = blockIdx.z;
    const int tid = threadIdx.x;
    const int ty = tid >> 4, tx = tid & 15;
    const int il = 3 * ty, jl = 6 * tx;

    const float4* srcA = (const float4*)(g_AB2 +
        ((size_t)(b * 512 + hs * 64)) * 96 + it * 48);
    const float4* srcC = (const float4*)(g_C2 +
        ((size_t)(b * 512 + hs * 64)) * 96);
    float4* dA = (float4*)As;
    float4* dC = (float4*)Cs;
#pragma unroll
    for (int t = tid; t < 768; t += 256) {
        int r = t / 12, q = t - r * 12;
        dA[t] = srcA[r * 24 + q];
    }
#pragma unroll
    for (int t = tid; t < 1536; t += 256)
        dC[t] = srcC[t];
    __syncthreads();

    const int bnd = min(max(g_Hpos - hs * 64, 0), 64);
    float acc[3][6] = {{0.f}};

    int h = 0;
#pragma unroll 4
    for (; h < bnd; h++) {
        const float* Ar = &As[h * 48 + il];
        const float* Cr = &Cs[h * 96 + jl];
        float a0 = Ar[0], a1 = Ar[1], a2 = Ar[2];
        float2 c01 = *(const float2*)&Cr[0];
        float2 c23 = *(const float2*)&Cr[2];
        float2 c45 = *(const float2*)&Cr[4];
        float cv[6] = {c01.x, c01.y, c23.x, c23.y, c45.x, c45.y};
#pragma unroll
        for (int c = 0; c < 6; c++) {
            acc[0][c] += fabsf(a0 + cv[c]);
            acc[1][c] += fabsf(a1 + cv[c]);
            acc[2][c] += fabsf(a2 + cv[c]);
        }
    }
#pragma unroll 4
    for (; h < 64; h++) {
        const float* Ar = &As[h * 48 + il];
        const float* Cr = &Cs[h * 96 + jl];
        float a0 = Ar[0], a1 = Ar[1], a2 = Ar[2];
        float2 c01 = *(const float2*)&Cr[0];
        float2 c23 = *(const float2*)&Cr[2];
        float2 c45 = *(const float2*)&Cr[4];
        float cv[6] = {c01.x, c01.y, c23.x, c23.y, c45.x, c45.y};
#pragma unroll
        for (int c = 0; c < 6; c++) {
            acc[0][c] -= fabsf(a0 + cv[c]);
            acc[1][c] -= fabsf(a1 + cv[c]);
            acc[2][c] -= fabsf(a2 + cv[c]);
        }
    }

    float* P = g_P + (size_t)hs * PSTRIDE +
               ((size_t)b * 96 + it * 48 + il) * 96 + jl;
#pragma unroll
    for (int r = 0; r < 3; r++) {
#pragma unroll
        for (int c = 0; c < 6; c += 2)
            *(float2*)&P[(size_t)r * 96 + c] = make_float2(acc[r][c], acc[r][c + 1]);
    }
}

// ---------------- kernel E: fused softmax-CE + final reduce -----------------
__global__ void ce_kernel(const int* __restrict__ order, float* __restrict__ out) {
    __shared__ int   ord[96];
    __shared__ float vsh[96];
    __shared__ float rowbuf[8][96];
    __shared__ float wpart[8];
    __shared__ int   slast;

    const int b = blockIdx.y, tid = threadIdx.x;
    const int warp = tid >> 5, lane = tid & 31;
    const int i = blockIdx.x * 8 + warp;

    if (tid < 96) {
        ord[tid] = order[b * 96 + tid];
        vsh[tid] = g_v4[0 * M_ + b * 96 + tid] + g_v4[1 * M_ + b * 96 + tid]
                 + g_v4[2 * M_ + b * 96 + tid] + g_v4[3 * M_ + b * 96 + tid];
    }
    __syncthreads();

    const size_t ro = ((size_t)b * 96 + i) * 96;
    float lg[3];
#pragma unroll
    for (int r = 0; r < 3; r++) {
        int j = lane + r * 32;
        float P = 0.f;
#pragma unroll
        for (int s = 0; s < NSLICE; s++)
            P += g_P[(size_t)s * PSTRIDE + ro + j];
        lg[r] = 0.55f * vsh[j] + 0.45f * P;
        rowbuf[warp][j] = lg[r];
    }

    float m = fmaxf(lg[0], fmaxf(lg[1], lg[2]));
#pragma unroll
    for (int o = 16; o > 0; o >>= 1)
        m = fmaxf(m, __shfl_xor_sync(0xffffffffu, m, o));
    float s = expf(lg[0] - m) + expf(lg[1] - m) + expf(lg[2] - m);
#pragma unroll
    for (int o = 16; o > 0; o >>= 1)
        s += __shfl_xor_sync(0xffffffffu, s, o);
    float lse = m + logf(s);

    int oi = ord[i];
    int o0 = ord[lane], o1 = ord[lane + 32], o2 = ord[lane + 64];
    unsigned t0 = __ballot_sync(0xffffffffu, o0 == oi + 1);
    unsigned t1 = __ballot_sync(0xffffffffu, o1 == oi + 1);
    unsigned t2 = __ballot_sync(0xffffffffu, o2 == oi + 1);
    int tgt = t0 ? (__ffs(t0) - 1)
                 : (t1 ? (31 + __ffs(t1)) : (t2 ? (63 + __ffs(t2)) : 0));

    int mx = max(o0, max(o1, o2));
#pragma unroll
    for (int o = 16; o > 0; o >>= 1)
        mx = max(mx, __shfl_xor_sync(0xffffffffu, mx, o));
    unsigned M0 = __ballot_sync(0xffffffffu, o0 == mx);
    unsigned M1 = __ballot_sync(0xffffffffu, o1 == mx);
    unsigned M2 = __ballot_sync(0xffffffffu, o2 == mx);
    int last = M0 ? (__ffs(M0) - 1) : (M1 ? (31 + __ffs(M1)) : (63 + __ffs(M2)));

    float contrib = (i == last) ? 0.f : (lse - rowbuf[warp][tgt]);
    if (lane == 0) wpart[warp] = contrib;
    __syncthreads();
    if (tid == 0) {
        float ssum = 0.f;
#pragma unroll
        for (int w = 0; w < 8; w++) ssum += wpart[w];
        g_partial[b * 12 + blockIdx.x] = ssum;
        __threadfence();
        slast = (atomicAdd(&g_ctr, 1) == NPART - 1) ? 1 : 0;
    }
    __syncthreads();

    if (slast) {
        __threadfence();
        __shared__ float wsum[8];
        float v = (tid < NPART) ? g_partial[tid] : 0.f;
#pragma unroll
        for (int o = 16; o > 0; o >>= 1)
            v += __shfl_xor_sync(0xffffffffu, v, o);
        if (lane == 0) wsum[warp] = v;
        __syncthreads();
        if (tid == 0) {
            float ss = 0.f;
#pragma unroll
            for (int k = 0; k < 8; k++) ss += wsum[k];
            out[0] = ss * (1.0f / (16.0f * 95.0f));
            g_ctr = 0;   // reset for next graph replay
        }
    }
}

// ---------------- launcher --------------------------------------------------
extern "C" void kernel_launch(void* const* d_in, const int* in_sizes, int n_in,
                              void* d_out, int out_size) {
    const float* X    = (const float*)d_in[0];
    const float* W1   = (const float*)d_in[1];
    const float* b1   = (const float*)d_in[2];
    const float* W2   = (const float*)d_in[3];
    const int*   order = (const int*)d_in[6];

    static bool attr_set = false;
    if (!attr_set) {
        cudaFuncSetAttribute(gemm_mma_kernel,
                             cudaFuncAttributeMaxDynamicSharedMemorySize, GEMM_SMEM);
        attr_set = true;
    }

    convert_kernel<<<896, 512>>>(X, W1, W2, b1);
    gemm_mma_kernel<<<dim3(8, 12), 256, GEMM_SMEM>>>();
    pairwise_kernel<<<dim3(NSLICE, 2, 16), 256>>>();
    ce_kernel<<<dim3(12, 16), 256>>>(order, (float*)d_out);
}